// round 2
// baseline (speedup 1.0000x reference)
#include <cuda_runtime.h>
#include <math.h>

#define BATCH 4
#define CDIM  64
#define KD    32
#define OD    64
#define NPIX  4096
#define KK    409          /* NPIX / TOPK */
#define ROWS  8
#define EPSF  1e-10f
#define LISTCAP 512
#define THREADS 1024

// ---------------- scratch (device globals: allocation-free) ----------------
__device__ __align__(16) float g_q[BATCH * KD * NPIX];   // [b][kd][n]
__device__ __align__(16) float g_k[BATCH * KD * NPIX];   // [b][kd][n]
__device__ __align__(16) float g_v[BATCH * NPIX * OD];   // [b][n][od]

// ---------------- f32x2 packed helpers (sm_10x) ----------------
__device__ __forceinline__ unsigned long long pack2(float a, float b) {
    unsigned long long r;
    asm("mov.b64 %0, {%1, %2};" : "=l"(r) : "f"(a), "f"(b));
    return r;
}
__device__ __forceinline__ void fma2(unsigned long long& d,
                                     unsigned long long a, unsigned long long b) {
    asm("fma.rn.f32x2 %0, %1, %2, %0;" : "+l"(d) : "l"(a), "l"(b));
}
__device__ __forceinline__ float2 unpack2(unsigned long long v) {
    float2 f;
    asm("mov.b64 {%0, %1}, %2;" : "=f"(f.x), "=f"(f.y) : "l"(v));
    return f;
}

__device__ __forceinline__ unsigned f2mono(float f) {
    unsigned u = __float_as_uint(f);
    return (u & 0x80000000u) ? ~u : (u | 0x80000000u);
}

// ---------------- kernel 0: fused QKV projection ----------------
__global__ void proj_kernel(const float* __restrict__ x,
                            const float* __restrict__ Wq, const float* __restrict__ bq,
                            const float* __restrict__ Wk, const float* __restrict__ bk,
                            const float* __restrict__ Wv, const float* __restrict__ bv)
{
    extern __shared__ float sm[];
    float* xs   = sm;                 // [64][128]
    float* Wall = xs + 64 * 128;      // [128][64]
    float* ball = Wall + 128 * 64;    // [128]

    const int b  = blockIdx.x >> 5;
    const int n0 = (blockIdx.x & 31) * 128;
    const int t  = threadIdx.x;

    for (int i = t; i < 32 * 64; i += 256) Wall[i] = Wq[i];
    for (int i = t; i < 32 * 64; i += 256) Wall[32 * 64 + i] = Wk[i];
    for (int i = t; i < 64 * 64; i += 256) Wall[64 * 64 + i] = Wv[i];
    if (t < 32)        ball[t] = bq[t];
    else if (t < 64)   ball[t] = bk[t - 32];
    else if (t < 128)  ball[t] = bv[t - 64];

    const float* xb = x + (size_t)b * CDIM * NPIX;
    for (int i = t; i < CDIM * 128; i += 256) {
        int c = i >> 7, p = i & 127;
        xs[c * 128 + p] = xb[(size_t)c * NPIX + n0 + p];
    }
    __syncthreads();

    const int p = t & 127;
    const int h = t >> 7;

    if (h == 0) {
        for (int oo = 0; oo < 64; oo++) {
            float acc = ball[oo];
            const float* wr = Wall + oo * 64;
            #pragma unroll 16
            for (int c = 0; c < 64; c++) acc = fmaf(wr[c], xs[c * 128 + p], acc);
            if (oo < 32) g_q[((size_t)b * KD + oo) * NPIX + n0 + p] = acc;
            else         g_k[((size_t)b * KD + (oo - 32)) * NPIX + n0 + p] = acc;
        }
    } else {
        float vacc[64];
        #pragma unroll
        for (int od = 0; od < 64; od++) vacc[od] = ball[64 + od];
        for (int c = 0; c < 64; c++) {
            float xv = xs[c * 128 + p];
            #pragma unroll
            for (int od = 0; od < 64; od++)
                vacc[od] = fmaf(Wall[(64 + od) * 64 + c], xv, vacc[od]);
        }
        float4* vd = (float4*)(g_v + ((size_t)b * NPIX + n0 + p) * OD);
        #pragma unroll
        for (int q4 = 0; q4 < 16; q4++)
            vd[q4] = make_float4(vacc[4 * q4], vacc[4 * q4 + 1], vacc[4 * q4 + 2], vacc[4 * q4 + 3]);
    }
}

// ---------------- kernel 1: energy + exact top-k threshold + masked softmax + PV ----------------
// grid: BATCH * (NPIX/ROWS) = 2048 CTAs, 1024 threads (4 warps per row)
__global__ void __launch_bounds__(THREADS, 1)
attn_kernel(const float* __restrict__ x, const float* __restrict__ gamma,
            float* __restrict__ out)
{
    extern __shared__ float sm[];
    float*    e      = sm;                                   // [ROWS][NPIX]
    float*    wl     = e + ROWS * NPIX;                      // [ROWS][LISTCAP]
    int*      il     = (int*)(wl + ROWS * LISTCAP);          // [ROWS][LISTCAP]
    int*      hist   = il + ROWS * LISTCAP;                  // [ROWS][256]
    float*    obuf4  = (float*)(hist + ROWS * 256);          // [ROWS][4][OD]
    float*    rowmax = obuf4 + ROWS * 4 * OD;                // [ROWS]
    float*    zsum   = rowmax + ROWS;                        // [ROWS]
    float*    wmax   = zsum + ROWS;                          // [32]
    unsigned* prefx  = (unsigned*)(wmax + 32);               // [ROWS]
    int*      remain = (int*)(prefx + ROWS);                 // [ROWS]
    int*      cnt    = remain + ROWS;                        // [ROWS]

    const int b  = blockIdx.x >> 9;
    const int i0 = (blockIdx.x & 511) * ROWS;
    const int t    = threadIdx.x;
    const int warp = t >> 5, lane = t & 31;
    const int r = warp >> 2, s = warp & 3;
    const int t128 = (s << 5) | lane;              // 0..127 within row group

    if (t < ROWS) { cnt[t] = 0; zsum[t] = 0.f; }

    // ---- q row in registers (broadcast loads) ----
    float qreg[KD];
    const float* qb = g_q + (size_t)b * KD * NPIX + i0 + r;
    #pragma unroll
    for (int kd = 0; kd < KD; kd++) qreg[kd] = qb[(size_t)kd * NPIX];

    // ---- phase E: energy row (packed f32x2 FMA) + running max ----
    const float4* k4 = (const float4*)(g_k + (size_t)b * KD * NPIX);
    float* erow = e + r * NPIX;
    float lmax = -1e30f;
    #pragma unroll
    for (int i = 0; i < 8; i++) {
        const int j4 = i * 128 + t128;
        unsigned long long acc01 = 0ull, acc23 = 0ull;
        #pragma unroll
        for (int kd = 0; kd < KD; kd++) {
            float4 kv = k4[kd * (NPIX / 4) + j4];
            unsigned long long qq = pack2(qreg[kd], qreg[kd]);
            unsigned long long k01 = pack2(kv.x, kv.y);
            unsigned long long k23 = pack2(kv.z, kv.w);
            fma2(acc01, k01, qq);
            fma2(acc23, k23, qq);
        }
        float2 a01 = unpack2(acc01), a23 = unpack2(acc23);
        ((float4*)erow)[j4] = make_float4(a01.x, a01.y, a23.x, a23.y);
        lmax = fmaxf(lmax, fmaxf(fmaxf(a01.x, a01.y), fmaxf(a23.x, a23.y)));
    }
    #pragma unroll
    for (int o = 16; o; o >>= 1) lmax = fmaxf(lmax, __shfl_xor_sync(0xffffffffu, lmax, o));
    if (lane == 0) wmax[warp] = lmax;
    __syncthreads();
    if (t < ROWS)
        rowmax[t] = fmaxf(fmaxf(wmax[4 * t], wmax[4 * t + 1]),
                          fmaxf(wmax[4 * t + 2], wmax[4 * t + 3]));
    __syncthreads();

    // ---- phase T: exact radix select of KK-th largest (4 x 8-bit, MSB first) ----
    unsigned pfx = 0;
    int rem = KK;
    int* h = hist + r * 256;
    for (int pass = 0; pass < 4; pass++) {
        for (int i = t128; i < 256; i += 128) h[i] = 0;
        __syncthreads();
        const int shift = 24 - 8 * pass;
        for (int j = t128; j < NPIX; j += 128) {
            unsigned u = f2mono(erow[j]);
            bool match = (pass == 0) || ((u >> (shift + 8)) == pfx);
            unsigned bin = (u >> shift) & 255u;
            unsigned key = match ? bin : 0xffffffffu;
            unsigned peers = __match_any_sync(0xffffffffu, key);
            if (match && lane == (__ffs(peers) - 1))
                atomicAdd(&h[bin], __popc(peers));
        }
        __syncthreads();
        if (s == 0) {
            // warp suffix scan: lane l covers bins [255-8l .. 248-8l] (descending)
            int lsum = 0;
            int b0 = 255 - 8 * lane;
            #pragma unroll
            for (int u2 = 0; u2 < 8; u2++) lsum += h[b0 - u2];
            int incl = lsum;
            #pragma unroll
            for (int o = 1; o < 32; o <<= 1) {
                int v = __shfl_up_sync(0xffffffffu, incl, o);
                if (lane >= o) incl += v;
            }
            int above = incl - lsum;
            if (above < rem && rem <= incl) {
                int cum = above, bsel = b0;
                #pragma unroll
                for (int u2 = 0; u2 < 8; u2++) {
                    int c = h[b0 - u2];
                    if (cum + c >= rem) { bsel = b0 - u2; break; }
                    cum += c;
                }
                prefx[r]  = (pfx << 8) | (unsigned)bsel;
                remain[r] = rem - cum;
            }
        }
        __syncthreads();
        pfx = prefx[r];
        rem = remain[r];
    }
    const unsigned Tu = pfx;   // exact mono bits of the KK-th largest energy

    // ---- phase W: mask + exp + warp-aggregated compaction; row sum Z ----
    const float m = rowmax[r];
    float zpart = 0.f;
    for (int j = t128; j < NPIX; j += 128) {
        float ev = erow[j];
        bool sel = (f2mono(ev) >= Tu);
        unsigned ball = __ballot_sync(0xffffffffu, sel);
        if (sel) {
            float w = __expf(ev - m);
            zpart += w;
            int ldr = __ffs(ball) - 1;
            int base = 0;
            if (lane == ldr) base = atomicAdd(&cnt[r], __popc(ball));
            base = __shfl_sync(ball, base, ldr);
            int pos = base + __popc(ball & ((1u << lane) - 1u));
            if (pos < LISTCAP) {
                il[r * LISTCAP + pos] = j;
                wl[r * LISTCAP + pos] = w;
            }
        }
    }
    #pragma unroll
    for (int o = 16; o; o >>= 1) zpart += __shfl_xor_sync(0xffffffffu, zpart, o);
    if (lane == 0) atomicAdd(&zsum[r], zpart);
    __syncthreads();

    // ---- phase PV: sparse gather of selected v columns (4 warps/row) ----
    int n = cnt[r]; if (n > LISTCAP) n = LISTCAP;
    const float* vb = g_v + (size_t)b * NPIX * OD;
    float2 o2 = make_float2(0.f, 0.f);
    for (int tix = s; tix < n; tix += 4) {
        int   j = il[r * LISTCAP + tix];
        float w = wl[r * LISTCAP + tix];
        float2 vv = ((const float2*)(vb + (size_t)j * OD))[lane];
        o2.x = fmaf(w, vv.x, o2.x);
        o2.y = fmaf(w, vv.y, o2.y);
    }
    ((float2*)(obuf4 + (r * 4 + s) * OD))[lane] = o2;
    __syncthreads();

    // ---- epilogue: reduce 4 partials, normalize, gamma, residual ----
    if (t < ROWS * CDIM) {
        const float g = gamma[0];
        const int r2 = t & 7, c = t >> 3;
        float acc = obuf4[(r2 * 4 + 0) * OD + c] + obuf4[(r2 * 4 + 1) * OD + c]
                  + obuf4[(r2 * 4 + 2) * OD + c] + obuf4[(r2 * 4 + 3) * OD + c];
        const float invZ = 1.f / (zsum[r2] + EPSF);
        const size_t oix = ((size_t)b * CDIM + c) * NPIX + i0 + r2;
        out[oix] = g * acc * invZ + x[oix];
    }
}

// ---------------- launch ----------------
extern "C" void kernel_launch(void* const* d_in, const int* in_sizes, int n_in,
                              void* d_out, int out_size)
{
    const float* x     = (const float*)d_in[0];
    const float* Wq    = (const float*)d_in[1];
    const float* bq    = (const float*)d_in[2];
    const float* Wk    = (const float*)d_in[3];
    const float* bk    = (const float*)d_in[4];
    const float* Wv    = (const float*)d_in[5];
    const float* bv    = (const float*)d_in[6];
    const float* gamma = (const float*)d_in[7];
    float* out = (float*)d_out;

    (void)in_sizes; (void)n_in; (void)out_size;

    const int SMEM_PROJ = (64 * 128 + 128 * 64 + 128) * 4;
    const int SMEM_ATTN = (ROWS * NPIX            // e
                         + ROWS * LISTCAP         // wl
                         + ROWS * LISTCAP         // il
                         + ROWS * 256             // hist
                         + ROWS * 4 * OD          // obuf4
                         + ROWS + ROWS + 32       // rowmax + zsum + wmax
                         + ROWS + ROWS + ROWS) * 4;

    cudaFuncSetAttribute(proj_kernel, cudaFuncAttributeMaxDynamicSharedMemorySize, SMEM_PROJ);
    cudaFuncSetAttribute(attn_kernel, cudaFuncAttributeMaxDynamicSharedMemorySize, SMEM_ATTN);

    proj_kernel<<<BATCH * 32, 256, SMEM_PROJ>>>(x, Wq, bq, Wk, bk, Wv, bv);
    attn_kernel<<<BATCH * (NPIX / ROWS), THREADS, SMEM_ATTN>>>(x, gamma, out);
}

// round 4
// speedup vs baseline: 1.1294x; 1.1294x over previous
#include <cuda_runtime.h>
#include <math.h>

#define BATCH 4
#define CDIM  64
#define KD    32
#define OD    64
#define NPIX  4096
#define KK    409
#define ROWS  8
#define EPSF  1e-10f
#define THREADS 512
#define LISTCAP 512
#define HPAD    264

// ---------------- scratch ----------------
__device__ __align__(16) float g_q[BATCH * KD * NPIX];   // [b][kd][n]
__device__ __align__(16) float g_k[BATCH * KD * NPIX];   // [b][kd][n]
__device__ __align__(16) float g_v[BATCH * NPIX * OD];   // [b][n][od]

// ---------------- f32x2 helpers ----------------
__device__ __forceinline__ unsigned long long pack2(float a, float b) {
    unsigned long long r;
    asm("mov.b64 %0, {%1, %2};" : "=l"(r) : "f"(a), "f"(b));
    return r;
}
__device__ __forceinline__ void fma2(unsigned long long& d,
                                     unsigned long long a, unsigned long long b) {
    asm("fma.rn.f32x2 %0, %1, %2, %0;" : "+l"(d) : "l"(a), "l"(b));
}
__device__ __forceinline__ float2 unpack2(unsigned long long v) {
    float2 f;
    asm("mov.b64 {%0, %1}, %2;" : "=f"(f.x), "=f"(f.y) : "l"(v));
    return f;
}
__device__ __forceinline__ unsigned f2mono(float f) {
    unsigned u = __float_as_uint(f);
    return (u & 0x80000000u) ? ~u : (u | 0x80000000u);
}

// ---------------- kernel 0: fused QKV projection (unchanged, proven) ----------------
__global__ void proj_kernel(const float* __restrict__ x,
                            const float* __restrict__ Wq, const float* __restrict__ bq,
                            const float* __restrict__ Wk, const float* __restrict__ bk,
                            const float* __restrict__ Wv, const float* __restrict__ bv)
{
    extern __shared__ float sm[];
    float* xs   = sm;                 // [64][128]
    float* Wall = xs + 64 * 128;      // [128][64]
    float* ball = Wall + 128 * 64;    // [128]

    const int b  = blockIdx.x >> 5;
    const int n0 = (blockIdx.x & 31) * 128;
    const int t  = threadIdx.x;

    for (int i = t; i < 32 * 64; i += 256) Wall[i] = Wq[i];
    for (int i = t; i < 32 * 64; i += 256) Wall[32 * 64 + i] = Wk[i];
    for (int i = t; i < 64 * 64; i += 256) Wall[64 * 64 + i] = Wv[i];
    if (t < 32)        ball[t] = bq[t];
    else if (t < 64)   ball[t] = bk[t - 32];
    else if (t < 128)  ball[t] = bv[t - 64];

    const float* xb = x + (size_t)b * CDIM * NPIX;
    for (int i = t; i < CDIM * 128; i += 256) {
        int c = i >> 7, p = i & 127;
        xs[c * 128 + p] = xb[(size_t)c * NPIX + n0 + p];
    }
    __syncthreads();

    const int p = t & 127;
    const int h = t >> 7;

    if (h == 0) {
        for (int oo = 0; oo < 64; oo++) {
            float acc = ball[oo];
            const float* wr = Wall + oo * 64;
            #pragma unroll 16
            for (int c = 0; c < 64; c++) acc = fmaf(wr[c], xs[c * 128 + p], acc);
            if (oo < 32) g_q[((size_t)b * KD + oo) * NPIX + n0 + p] = acc;
            else         g_k[((size_t)b * KD + (oo - 32)) * NPIX + n0 + p] = acc;
        }
    } else {
        float vacc[64];
        #pragma unroll
        for (int od = 0; od < 64; od++) vacc[od] = ball[64 + od];
        for (int c = 0; c < 64; c++) {
            float xv = xs[c * 128 + p];
            #pragma unroll
            for (int od = 0; od < 64; od++)
                vacc[od] = fmaf(Wall[(64 + od) * 64 + c], xv, vacc[od]);
        }
        float4* vd = (float4*)(g_v + ((size_t)b * NPIX + n0 + p) * OD);
        #pragma unroll
        for (int q4 = 0; q4 < 16; q4++)
            vd[q4] = make_float4(vacc[4 * q4], vacc[4 * q4 + 1], vacc[4 * q4 + 2], vacc[4 * q4 + 3]);
    }
}

// ---------------- kernel 1 ----------------
// grid: BATCH*512 CTAs, 512 threads, 8 rows/CTA (64 threads = 2 warps per row
// in selection/PV phases; energy is 8x8 register-blocked per thread).
__global__ void __launch_bounds__(THREADS, 1)
attn_kernel(const float* __restrict__ x, const float* __restrict__ gamma,
            float* __restrict__ out)
{
    extern __shared__ float sm[];
    float*    e      = sm;                                   // [8][4096]
    float*    qs     = e + ROWS * NPIX;                      // [8][32]
    float*    wl     = qs + ROWS * KD;                       // [8][LISTCAP]
    int*      il     = (int*)(wl + ROWS * LISTCAP);          // [8][LISTCAP]
    int*      hist   = il + ROWS * LISTCAP;                  // [8][HPAD]
    float*    obuf   = (float*)(hist + ROWS * HPAD);         // [8][2][64]
    float*    wmaxs  = obuf + ROWS * 2 * OD;                 // [16][8]
    float*    rowmax = wmaxs + 16 * ROWS;                    // [8]
    float*    zsum   = rowmax + ROWS;                        // [8]
    unsigned* pfxs   = (unsigned*)(zsum + ROWS);             // [8]
    int*      rems   = (int*)(pfxs + ROWS);                  // [8]
    int*      cnt    = rems + ROWS;                          // [8]

    const int b  = blockIdx.x >> 9;
    const int i0 = (blockIdx.x & 511) * ROWS;
    const int t    = threadIdx.x;
    const int lane = t & 31;
    const int warp = t >> 5;

    if (t < ROWS) { cnt[t] = 0; zsum[t] = 0.f; }
    if (t < ROWS * KD) {
        int kd = t & 31, rr = t >> 5;
        qs[rr * 32 + kd] = g_q[((size_t)b * KD + kd) * NPIX + i0 + rr];
    }
    __syncthreads();

    // ===== phase E: energy, 8 rows x 8 cols per thread, f32x2, K read once =====
    {
        const ulonglong2* kq = (const ulonglong2*)(g_k + (size_t)b * KD * NPIX);
        unsigned long long acc[ROWS][4];
        #pragma unroll
        for (int r = 0; r < ROWS; r++)
            #pragma unroll
            for (int c = 0; c < 4; c++) acc[r][c] = 0ull;

        for (int kd = 0; kd < KD; kd++) {          // NO unroll: keep K regs minimal
            ulonglong2 ka = kq[kd * (NPIX / 4) + 2 * t];       // floats 8t..8t+3
            ulonglong2 kb = kq[kd * (NPIX / 4) + 2 * t + 1];   // floats 8t+4..8t+7
            const float* qcol = qs + kd;
            #pragma unroll
            for (int r = 0; r < ROWS; r++) {
                float qv = qcol[r * 32];
                unsigned long long qq = pack2(qv, qv);
                fma2(acc[r][0], ka.x, qq);
                fma2(acc[r][1], ka.y, qq);
                fma2(acc[r][2], kb.x, qq);
                fma2(acc[r][3], kb.y, qq);
            }
        }

        // epilogue: store e rows + per-row max
        float rmax[ROWS];
        #pragma unroll
        for (int r = 0; r < ROWS; r++) {
            float2 p0 = unpack2(acc[r][0]), p1 = unpack2(acc[r][1]);
            float2 p2 = unpack2(acc[r][2]), p3 = unpack2(acc[r][3]);
            float4* ep = (float4*)(e + r * NPIX + 8 * t);
            ep[0] = make_float4(p0.x, p0.y, p1.x, p1.y);
            ep[1] = make_float4(p2.x, p2.y, p3.x, p3.y);
            float mx = fmaxf(fmaxf(fmaxf(p0.x, p0.y), fmaxf(p1.x, p1.y)),
                             fmaxf(fmaxf(p2.x, p2.y), fmaxf(p3.x, p3.y)));
            rmax[r] = mx;
        }
        #pragma unroll
        for (int r = 0; r < ROWS; r++) {
            float m = rmax[r];
            #pragma unroll
            for (int o = 16; o; o >>= 1) m = fmaxf(m, __shfl_xor_sync(0xffffffffu, m, o));
            if (lane == 0) wmaxs[warp * ROWS + r] = m;
        }
    }
    __syncthreads();
    if (t < ROWS) {
        float m = wmaxs[t];
        #pragma unroll
        for (int w = 1; w < 16; w++) m = fmaxf(m, wmaxs[w * ROWS + t]);
        rowmax[t] = m;
    }

    // ===== phase T: exact radix select of KK-th largest (4 x 8-bit, MSB first) =====
    const int r   = t >> 6;       // row served by this thread (2 warps per row)
    const int t64 = t & 63;
    float* erow = e + r * NPIX;
    {
        unsigned pfx = 0;
        int rem = KK;
        int* h = hist + r * HPAD;
        for (int pass = 0; pass < 4; pass++) {
            for (int i = t64; i < 256; i += 64) h[i] = 0;
            __syncthreads();
            const int shift = 24 - 8 * pass;
            for (int j = t64; j < NPIX; j += 64) {
                unsigned u = f2mono(erow[j]);
                bool match = (pass == 0) || ((u >> (shift + 8)) == pfx);
                unsigned bin = (u >> shift) & 255u;
                unsigned key = match ? bin : 0xffffffffu;
                unsigned peers = __match_any_sync(0xffffffffu, key);
                if (match && lane == (__ffs(peers) - 1))
                    atomicAdd(&h[bin], __popc(peers));
            }
            __syncthreads();
            if (t64 < 32) {   // one full warp per row
                int lsum = 0;
                int bb0 = 255 - 8 * lane;
                #pragma unroll
                for (int u2 = 0; u2 < 8; u2++) lsum += h[bb0 - u2];
                int incl = lsum;
                #pragma unroll
                for (int o = 1; o < 32; o <<= 1) {
                    int vv = __shfl_up_sync(0xffffffffu, incl, o);
                    if (lane >= o) incl += vv;
                }
                int above = incl - lsum;
                if (above < rem && rem <= incl) {
                    int cum = above, bsel = bb0;
                    #pragma unroll
                    for (int u2 = 0; u2 < 8; u2++) {
                        int c = h[bb0 - u2];
                        if (cum + c >= rem) { bsel = bb0 - u2; break; }
                        cum += c;
                    }
                    pfxs[r] = (pfx << 8) | (unsigned)bsel;
                    rems[r] = rem - cum;
                }
            }
            __syncthreads();
            pfx = pfxs[r];
            rem = rems[r];
        }

        // ===== phase W: mask + exp + aggregated compaction; row sum Z =====
        const unsigned Tu = pfx;
        const float m = rowmax[r];
        float zpart = 0.f;
        for (int j = t64; j < NPIX; j += 64) {
            float ev = erow[j];
            bool sel = (f2mono(ev) >= Tu);
            unsigned bs = __ballot_sync(0xffffffffu, sel);
            if (sel) {
                float w = __expf(ev - m);
                zpart += w;
                int ldr = __ffs(bs) - 1, base = 0;
                if (lane == ldr) base = atomicAdd(&cnt[r], __popc(bs));
                base = __shfl_sync(bs, base, ldr);
                int pos = base + __popc(bs & ((1u << lane) - 1u));
                if (pos < LISTCAP) {
                    il[r * LISTCAP + pos] = j;
                    wl[r * LISTCAP + pos] = w;
                }
            }
        }
        #pragma unroll
        for (int o = 16; o; o >>= 1) zpart += __shfl_xor_sync(0xffffffffu, zpart, o);
        if (lane == 0) atomicAdd(&zsum[r], zpart);
    }
    __syncthreads();

    // ===== phase PV: sparse gather, 2 warps/row, x4 unroll for MLP =====
    {
        int n = cnt[r]; if (n > LISTCAP) n = LISTCAP;
        const int s = t64 >> 5;
        const float* vb = g_v + (size_t)b * NPIX * OD;
        const int*   ilr = il + r * LISTCAP;
        const float* wlr = wl + r * LISTCAP;

        int half  = (n + 1) >> 1;
        int start = s * half;
        int end   = start + half; if (end > n) end = n;

        float2 o2 = make_float2(0.f, 0.f);
        int tix = start;
        for (; tix + 4 <= end; tix += 4) {
            int j0 = ilr[tix], j1 = ilr[tix + 1], j2 = ilr[tix + 2], j3 = ilr[tix + 3];
            float w0 = wlr[tix], w1 = wlr[tix + 1], w2 = wlr[tix + 2], w3 = wlr[tix + 3];
            float2 v0 = ((const float2*)(vb + (size_t)j0 * OD))[lane];
            float2 v1 = ((const float2*)(vb + (size_t)j1 * OD))[lane];
            float2 v2 = ((const float2*)(vb + (size_t)j2 * OD))[lane];
            float2 v3 = ((const float2*)(vb + (size_t)j3 * OD))[lane];
            o2.x = fmaf(w0, v0.x, o2.x); o2.y = fmaf(w0, v0.y, o2.y);
            o2.x = fmaf(w1, v1.x, o2.x); o2.y = fmaf(w1, v1.y, o2.y);
            o2.x = fmaf(w2, v2.x, o2.x); o2.y = fmaf(w2, v2.y, o2.y);
            o2.x = fmaf(w3, v3.x, o2.x); o2.y = fmaf(w3, v3.y, o2.y);
        }
        for (; tix < end; tix++) {
            int jj = ilr[tix];
            float w = wlr[tix];
            float2 vv = ((const float2*)(vb + (size_t)jj * OD))[lane];
            o2.x = fmaf(w, vv.x, o2.x); o2.y = fmaf(w, vv.y, o2.y);
        }
        ((float2*)(obuf + (r * 2 + s) * OD))[lane] = o2;
    }
    __syncthreads();

    // ===== epilogue =====
    {
        const float g = gamma[0];
        const int r2 = t & 7, c = t >> 3;
        float a = obuf[(r2 * 2 + 0) * OD + c] + obuf[(r2 * 2 + 1) * OD + c];
        const float invZ = 1.f / (zsum[r2] + EPSF);
        const size_t oix = ((size_t)b * CDIM + c) * NPIX + i0 + r2;
        out[oix] = g * a * invZ + x[oix];
    }
}

// ---------------- launch ----------------
extern "C" void kernel_launch(void* const* d_in, const int* in_sizes, int n_in,
                              void* d_out, int out_size)
{
    const float* x     = (const float*)d_in[0];
    const float* Wq    = (const float*)d_in[1];
    const float* bq    = (const float*)d_in[2];
    const float* Wk    = (const float*)d_in[3];
    const float* bk    = (const float*)d_in[4];
    const float* Wv    = (const float*)d_in[5];
    const float* bv    = (const float*)d_in[6];
    const float* gamma = (const float*)d_in[7];
    float* out = (float*)d_out;

    (void)in_sizes; (void)n_in; (void)out_size;

    const int SMEM_PROJ = (64 * 128 + 128 * 64 + 128) * 4;
    const int SMEM_ATTN = (ROWS * NPIX          // e
                         + ROWS * KD            // qs
                         + ROWS * LISTCAP       // wl
                         + ROWS * LISTCAP       // il
                         + ROWS * HPAD          // hist
                         + ROWS * 2 * OD        // obuf
                         + 16 * ROWS            // wmaxs
                         + ROWS * 5) * 4;       // rowmax,zsum,pfxs,rems,cnt

    cudaFuncSetAttribute(proj_kernel, cudaFuncAttributeMaxDynamicSharedMemorySize, SMEM_PROJ);
    cudaFuncSetAttribute(attn_kernel, cudaFuncAttributeMaxDynamicSharedMemorySize, SMEM_ATTN);

    proj_kernel<<<BATCH * 32, 256, SMEM_PROJ>>>(x, Wq, bq, Wk, bk, Wv, bv);
    attn_kernel<<<BATCH * (NPIX / ROWS), THREADS, SMEM_ATTN>>>(x, gamma, out);
}

// round 6
// speedup vs baseline: 1.1677x; 1.0339x over previous
#include <cuda_runtime.h>
#include <math.h>

#define BATCH 4
#define CDIM  64
#define KD    32
#define OD    64
#define NPIX  4096
#define KK    409
#define ROWS  8
#define EPSF  1e-10f
#define THREADS 512
#define LISTCAP 448
#define CANDCAP 1280
#define HPAD    264

// ---------------- scratch ----------------
__device__ __align__(16) float g_q[BATCH * KD * NPIX];   // [b][kd][n]
__device__ __align__(16) float g_k[BATCH * KD * NPIX];   // [b][kd][n]
__device__ __align__(16) float g_v[BATCH * NPIX * OD];   // [b][n][od]

// ---------------- f32x2 helpers ----------------
__device__ __forceinline__ unsigned long long pack2(float a, float b) {
    unsigned long long r;
    asm("mov.b64 %0, {%1, %2};" : "=l"(r) : "f"(a), "f"(b));
    return r;
}
__device__ __forceinline__ void fma2(unsigned long long& d,
                                     unsigned long long a, unsigned long long b) {
    asm("fma.rn.f32x2 %0, %1, %2, %0;" : "+l"(d) : "l"(a), "l"(b));
}
__device__ __forceinline__ float2 unpack2(unsigned long long v) {
    float2 f;
    asm("mov.b64 {%0, %1}, %2;" : "=f"(f.x), "=f"(f.y) : "l"(v));
    return f;
}
__device__ __forceinline__ unsigned f2mono(float f) {
    unsigned u = __float_as_uint(f);
    return (u & 0x80000000u) ? ~u : (u | 0x80000000u);
}

// ---------------- kernel 0: fused QKV projection (proven) ----------------
__global__ void proj_kernel(const float* __restrict__ x,
                            const float* __restrict__ Wq, const float* __restrict__ bq,
                            const float* __restrict__ Wk, const float* __restrict__ bk,
                            const float* __restrict__ Wv, const float* __restrict__ bv)
{
    extern __shared__ float sm[];
    float* xs   = sm;                 // [64][128]
    float* Wall = xs + 64 * 128;      // [128][64]
    float* ball = Wall + 128 * 64;    // [128]

    const int b  = blockIdx.x >> 5;
    const int n0 = (blockIdx.x & 31) * 128;
    const int t  = threadIdx.x;

    for (int i = t; i < 32 * 64; i += 256) Wall[i] = Wq[i];
    for (int i = t; i < 32 * 64; i += 256) Wall[32 * 64 + i] = Wk[i];
    for (int i = t; i < 64 * 64; i += 256) Wall[64 * 64 + i] = Wv[i];
    if (t < 32)        ball[t] = bq[t];
    else if (t < 64)   ball[t] = bk[t - 32];
    else if (t < 128)  ball[t] = bv[t - 64];

    const float* xb = x + (size_t)b * CDIM * NPIX;
    for (int i = t; i < CDIM * 128; i += 256) {
        int c = i >> 7, p = i & 127;
        xs[c * 128 + p] = xb[(size_t)c * NPIX + n0 + p];
    }
    __syncthreads();

    const int p = t & 127;
    const int h = t >> 7;

    if (h == 0) {
        for (int oo = 0; oo < 64; oo++) {
            float acc = ball[oo];
            const float* wr = Wall + oo * 64;
            #pragma unroll 16
            for (int c = 0; c < 64; c++) acc = fmaf(wr[c], xs[c * 128 + p], acc);
            if (oo < 32) g_q[((size_t)b * KD + oo) * NPIX + n0 + p] = acc;
            else         g_k[((size_t)b * KD + (oo - 32)) * NPIX + n0 + p] = acc;
        }
    } else {
        float vacc[64];
        #pragma unroll
        for (int od = 0; od < 64; od++) vacc[od] = ball[64 + od];
        for (int c = 0; c < 64; c++) {
            float xv = xs[c * 128 + p];
            #pragma unroll
            for (int od = 0; od < 64; od++)
                vacc[od] = fmaf(Wall[(64 + od) * 64 + c], xv, vacc[od]);
        }
        float4* vd = (float4*)(g_v + ((size_t)b * NPIX + n0 + p) * OD);
        #pragma unroll
        for (int q4 = 0; q4 < 16; q4++)
            vd[q4] = make_float4(vacc[4 * q4], vacc[4 * q4 + 1], vacc[4 * q4 + 2], vacc[4 * q4 + 3]);
    }
}

// ---------------- kernel 1 ----------------
// grid: BATCH*512 CTAs, 512 threads, 8 rows/CTA.
__global__ void __launch_bounds__(THREADS, 1)
attn_kernel(const float* __restrict__ x, const float* __restrict__ gamma,
            float* __restrict__ out)
{
    extern __shared__ float sm[];
    float*          e      = sm;                               // [8][4096]
    float*          qs     = e + ROWS * NPIX;                  // [8][32]
    float*          wl     = qs + ROWS * KD;                   // [8][LISTCAP]
    int*            il     = (int*)(wl + ROWS * LISTCAP);      // [8][LISTCAP]
    unsigned short* cdi    = (unsigned short*)(il + ROWS * LISTCAP); // [8][CANDCAP]
    int*            hist   = (int*)(cdi + ROWS * CANDCAP);     // [8][HPAD]
    float*          obuf   = (float*)(hist + ROWS * HPAD);     // [8][2][64]
    float*          wmaxs  = obuf + ROWS * 2 * OD;             // [16][8]
    float*          rowmax = wmaxs + 16 * ROWS;                // [8]
    float*          zsum   = rowmax + ROWS;                    // [8]
    unsigned*       b0s    = (unsigned*)(zsum + ROWS);         // [8]
    int*            rem1   = (int*)(b0s + ROWS);               // [8]
    unsigned*       pfxs   = (unsigned*)(rem1 + ROWS);         // [8]
    int*            rems   = (int*)(pfxs + ROWS);              // [8]
    int*            cnt    = rems + ROWS;                      // [8]
    int*            ccnt   = cnt + ROWS;                       // [8]

    const int b  = blockIdx.x >> 9;
    const int i0 = (blockIdx.x & 511) * ROWS;
    const int t    = threadIdx.x;
    const int lane = t & 31;
    const int warp = t >> 5;

    if (t < ROWS) { cnt[t] = 0; ccnt[t] = 0; zsum[t] = 0.f; }
    for (int i = t; i < ROWS * HPAD; i += THREADS) hist[i] = 0;
    if (t < ROWS * KD) {
        int kd = t & 31, rr = t >> 5;
        qs[rr * 32 + kd] = g_q[((size_t)b * KD + kd) * NPIX + i0 + rr];
    }
    __syncthreads();

    // ===== phase E: energy, 8 rows x 8 cols per thread (R4-proven) =====
    {
        const ulonglong2* kq = (const ulonglong2*)(g_k + (size_t)b * KD * NPIX);
        unsigned long long acc[ROWS][4];
        #pragma unroll
        for (int r = 0; r < ROWS; r++)
            #pragma unroll
            for (int c = 0; c < 4; c++) acc[r][c] = 0ull;

        for (int kd = 0; kd < KD; kd++) {          // NO unroll: keep regs minimal
            ulonglong2 ka = kq[kd * (NPIX / 4) + 2 * t];
            ulonglong2 kb = kq[kd * (NPIX / 4) + 2 * t + 1];
            const float* qcol = qs + kd;
            #pragma unroll
            for (int r = 0; r < ROWS; r++) {
                float qv = qcol[r * 32];
                unsigned long long qq = pack2(qv, qv);
                fma2(acc[r][0], ka.x, qq);
                fma2(acc[r][1], ka.y, qq);
                fma2(acc[r][2], kb.x, qq);
                fma2(acc[r][3], kb.y, qq);
            }
        }

        // epilogue: store e, per-row max, AND top-byte histogram from registers
        #pragma unroll
        for (int r = 0; r < ROWS; r++) {
            float2 p0 = unpack2(acc[r][0]), p1 = unpack2(acc[r][1]);
            float2 p2 = unpack2(acc[r][2]), p3 = unpack2(acc[r][3]);
            float4* ep = (float4*)(e + r * NPIX + 8 * t);
            ep[0] = make_float4(p0.x, p0.y, p1.x, p1.y);
            ep[1] = make_float4(p2.x, p2.y, p3.x, p3.y);
            float m = fmaxf(fmaxf(fmaxf(p0.x, p0.y), fmaxf(p1.x, p1.y)),
                            fmaxf(fmaxf(p2.x, p2.y), fmaxf(p3.x, p3.y)));
            #pragma unroll
            for (int o = 16; o; o >>= 1) m = fmaxf(m, __shfl_xor_sync(0xffffffffu, m, o));
            if (lane == 0) wmaxs[warp * ROWS + r] = m;

            int* h = hist + r * HPAD;
            float vals[8] = {p0.x, p0.y, p1.x, p1.y, p2.x, p2.y, p3.x, p3.y};
            #pragma unroll
            for (int i = 0; i < 8; i++) {
                unsigned bx = f2mono(vals[i]) >> 24;
                unsigned peers = __match_any_sync(0xffffffffu, bx);
                if (lane == (__ffs(peers) - 1)) atomicAdd(&h[(int)bx], __popc(peers));
            }
        }
    }
    __syncthreads();
    if (t < ROWS) {
        float m = wmaxs[t];
        #pragma unroll
        for (int w = 1; w < 16; w++) m = fmaxf(m, wmaxs[w * ROWS + t]);
        rowmax[t] = m;
    }
    __syncthreads();

    // ===== boundary bin b0 per row (warp w = row w) =====
    if (warp < ROWS) {
        const int rr = warp;
        int* h = hist + rr * HPAD;
        int lsum = 0;
        int bb0 = 255 - 8 * lane;
        #pragma unroll
        for (int u2 = 0; u2 < 8; u2++) lsum += h[bb0 - u2];
        int incl = lsum;
        #pragma unroll
        for (int o = 1; o < 32; o <<= 1) {
            int vv = __shfl_up_sync(0xffffffffu, incl, o);
            if (lane >= o) incl += vv;
        }
        int above = incl - lsum;
        if (above < KK && KK <= incl) {
            int cum = above, bsel = bb0;
            #pragma unroll
            for (int u2 = 0; u2 < 8; u2++) {
                int c = h[bb0 - u2];
                if (cum + c >= KK) { bsel = bb0 - u2; break; }
                cum += c;
            }
            b0s[rr]  = (unsigned)bsel;
            rem1[rr] = KK - cum;
        }
    }
    __syncthreads();

    // ===== classify scan over e (ONE pass, uniform trips) =====
    const int rg  = t >> 6;       // 64 threads (2 warps) per row
    const int t64 = t & 63;
    float* erow = e + rg * NPIX;
    const float m = rowmax[rg];
    const unsigned B0 = b0s[rg];
    float zpart = 0.f;
    for (int j = t64; j < NPIX; j += 64) {
        float v = erow[j];
        unsigned u = f2mono(v);
        unsigned byt = u >> 24;
        bool sure = (byt > B0);
        unsigned bs = __ballot_sync(0xffffffffu, sure);
        if (sure) {
            float w = __expf(v - m);
            zpart += w;
            int ldr = __ffs(bs) - 1, base = 0;
            if (lane == ldr) base = atomicAdd(&cnt[rg], __popc(bs));
            base = __shfl_sync(bs, base, ldr);
            int pos = base + __popc(bs & ((1u << lane) - 1u));
            if (pos < LISTCAP) { il[rg * LISTCAP + pos] = j; wl[rg * LISTCAP + pos] = w; }
        }
        bool cand = (byt == B0);
        unsigned bc = __ballot_sync(0xffffffffu, cand);
        if (cand) {
            int ldr = __ffs(bc) - 1, base = 0;
            if (lane == ldr) base = atomicAdd(&ccnt[rg], __popc(bc));
            base = __shfl_sync(bc, base, ldr);
            int pos = base + __popc(bc & ((1u << lane) - 1u));
            if (pos < CANDCAP) cdi[rg * CANDCAP + pos] = (unsigned short)j;
        }
    }
    __syncthreads();

    // ===== 3-pass radix over candidates (PADDED loops: hang fix) =====
    {
        int C = ccnt[rg]; if (C > CANDCAP) C = CANDCAP;
        const int Cpad = (C + 63) & ~63;
        unsigned pfx = B0;
        int rem = rem1[rg];
        int* h = hist + rg * HPAD;
        const unsigned short* cdr = cdi + rg * CANDCAP;

        for (int pass = 0; pass < 3; pass++) {
            for (int i = t64; i < 256; i += 64) h[i] = 0;
            __syncthreads();
            const int shift = 16 - 8 * pass;
            for (int i = t64; i < Cpad; i += 64) {
                bool valid = (i < C);
                unsigned u = 0;
                if (valid) u = f2mono(erow[cdr[i]]);
                bool match = valid && ((u >> (shift + 8)) == pfx);
                unsigned bin = (u >> shift) & 255u;
                unsigned key = match ? bin : 0xffffffffu;
                unsigned peers = __match_any_sync(0xffffffffu, key);
                if (match && lane == (__ffs(peers) - 1))
                    atomicAdd(&h[bin], __popc(peers));
            }
            __syncthreads();
            if (t64 < 32) {
                int lsum = 0;
                int bb0 = 255 - 8 * lane;
                #pragma unroll
                for (int u2 = 0; u2 < 8; u2++) lsum += h[bb0 - u2];
                int incl = lsum;
                #pragma unroll
                for (int o = 1; o < 32; o <<= 1) {
                    int vv = __shfl_up_sync(0xffffffffu, incl, o);
                    if (lane >= o) incl += vv;
                }
                int above = incl - lsum;
                if (above < rem && rem <= incl) {
                    int cum = above, bsel = bb0;
                    #pragma unroll
                    for (int u2 = 0; u2 < 8; u2++) {
                        int c = h[bb0 - u2];
                        if (cum + c >= rem) { bsel = bb0 - u2; break; }
                        cum += c;
                    }
                    pfxs[rg] = (pfx << 8) | (unsigned)bsel;
                    rems[rg] = rem - cum;
                }
            }
            __syncthreads();
            pfx = pfxs[rg];
            rem = rems[rg];
        }

        // ===== final candidate scan: u >= exact 32-bit threshold =====
        const unsigned T = pfx;
        for (int i = t64; i < Cpad; i += 64) {
            bool valid = (i < C);
            int idx = valid ? (int)cdr[i] : 0;
            float v = 0.f;
            unsigned u = 0;
            if (valid) { v = erow[idx]; u = f2mono(v); }
            bool sel = valid && (u >= T);
            unsigned bs = __ballot_sync(0xffffffffu, sel);
            if (sel) {
                float w = __expf(v - m);
                zpart += w;
                int ldr = __ffs(bs) - 1, base = 0;
                if (lane == ldr) base = atomicAdd(&cnt[rg], __popc(bs));
                base = __shfl_sync(bs, base, ldr);
                int pos = base + __popc(bs & ((1u << lane) - 1u));
                if (pos < LISTCAP) { il[rg * LISTCAP + pos] = idx; wl[rg * LISTCAP + pos] = w; }
            }
        }
    }
    #pragma unroll
    for (int o = 16; o; o >>= 1) zpart += __shfl_xor_sync(0xffffffffu, zpart, o);
    if (lane == 0) atomicAdd(&zsum[rg], zpart);
    __syncthreads();

    // ===== phase PV: sparse gather, 2 warps/row, x4 unroll (R4-proven) =====
    {
        int n = cnt[rg]; if (n > LISTCAP) n = LISTCAP;
        const int s = t64 >> 5;
        const float* vb = g_v + (size_t)b * NPIX * OD;
        const int*   ilr = il + rg * LISTCAP;
        const float* wlr = wl + rg * LISTCAP;

        int half  = (n + 1) >> 1;
        int start = s * half;
        int end   = start + half; if (end > n) end = n;

        float2 o2 = make_float2(0.f, 0.f);
        int tix = start;
        for (; tix + 4 <= end; tix += 4) {
            int j0 = ilr[tix], j1 = ilr[tix + 1], j2 = ilr[tix + 2], j3 = ilr[tix + 3];
            float w0 = wlr[tix], w1 = wlr[tix + 1], w2 = wlr[tix + 2], w3 = wlr[tix + 3];
            float2 v0 = ((const float2*)(vb + (size_t)j0 * OD))[lane];
            float2 v1 = ((const float2*)(vb + (size_t)j1 * OD))[lane];
            float2 v2 = ((const float2*)(vb + (size_t)j2 * OD))[lane];
            float2 v3 = ((const float2*)(vb + (size_t)j3 * OD))[lane];
            o2.x = fmaf(w0, v0.x, o2.x); o2.y = fmaf(w0, v0.y, o2.y);
            o2.x = fmaf(w1, v1.x, o2.x); o2.y = fmaf(w1, v1.y, o2.y);
            o2.x = fmaf(w2, v2.x, o2.x); o2.y = fmaf(w2, v2.y, o2.y);
            o2.x = fmaf(w3, v3.x, o2.x); o2.y = fmaf(w3, v3.y, o2.y);
        }
        for (; tix < end; tix++) {
            int jj = ilr[tix];
            float w = wlr[tix];
            float2 vv = ((const float2*)(vb + (size_t)jj * OD))[lane];
            o2.x = fmaf(w, vv.x, o2.x); o2.y = fmaf(w, vv.y, o2.y);
        }
        ((float2*)(obuf + (rg * 2 + s) * OD))[lane] = o2;
    }
    __syncthreads();

    // ===== epilogue =====
    {
        const float g = gamma[0];
        const int r2 = t & 7, c = t >> 3;
        float a = obuf[(r2 * 2 + 0) * OD + c] + obuf[(r2 * 2 + 1) * OD + c];
        const float invZ = 1.f / (zsum[r2] + EPSF);
        const size_t oix = ((size_t)b * CDIM + c) * NPIX + i0 + r2;
        out[oix] = g * a * invZ + x[oix];
    }
}

// ---------------- launch ----------------
extern "C" void kernel_launch(void* const* d_in, const int* in_sizes, int n_in,
                              void* d_out, int out_size)
{
    const float* x     = (const float*)d_in[0];
    const float* Wq    = (const float*)d_in[1];
    const float* bq    = (const float*)d_in[2];
    const float* Wk    = (const float*)d_in[3];
    const float* bk    = (const float*)d_in[4];
    const float* Wv    = (const float*)d_in[5];
    const float* bv    = (const float*)d_in[6];
    const float* gamma = (const float*)d_in[7];
    float* out = (float*)d_out;

    (void)in_sizes; (void)n_in; (void)out_size;

    const int SMEM_PROJ = (64 * 128 + 128 * 64 + 128) * 4;
    const int SMEM_ATTN = (ROWS * NPIX              // e
                         + ROWS * KD                // qs
                         + ROWS * LISTCAP           // wl
                         + ROWS * LISTCAP           // il
                         + ROWS * HPAD              // hist
                         + ROWS * 2 * OD            // obuf
                         + 16 * ROWS                // wmaxs
                         + ROWS * 8) * 4            // rowmax,zsum,b0s,rem1,pfxs,rems,cnt,ccnt
                         + ROWS * CANDCAP * 2;      // cdi (u16)

    cudaFuncSetAttribute(proj_kernel, cudaFuncAttributeMaxDynamicSharedMemorySize, SMEM_PROJ);
    cudaFuncSetAttribute(attn_kernel, cudaFuncAttributeMaxDynamicSharedMemorySize, SMEM_ATTN);

    proj_kernel<<<BATCH * 32, 256, SMEM_PROJ>>>(x, Wq, bq, Wk, bk, Wv, bv);
    attn_kernel<<<BATCH * (NPIX / ROWS), THREADS, SMEM_ATTN>>>(x, gamma, out);
}

// round 7
// speedup vs baseline: 1.2218x; 1.0464x over previous
#include <cuda_runtime.h>
#include <math.h>

#define BATCH 4
#define CDIM  64
#define KD    32
#define OD    64
#define NPIX  4096
#define KK    409
#define ROWS  4
#define EPSF  1e-10f
#define THREADS 256
#define LISTCAP 448
#define CANDCAP 1024
#define NBIN0   1024
#define HPAD    1032

// ---------------- scratch ----------------
__device__ __align__(16) float g_q[BATCH * KD * NPIX];   // [b][kd][n]
__device__ __align__(16) float g_k[BATCH * KD * NPIX];   // [b][kd][n]
__device__ __align__(16) float g_v[BATCH * NPIX * OD];   // [b][n][od]

// ---------------- f32x2 helpers ----------------
__device__ __forceinline__ unsigned long long pack2(float a, float b) {
    unsigned long long r;
    asm("mov.b64 %0, {%1, %2};" : "=l"(r) : "f"(a), "f"(b));
    return r;
}
__device__ __forceinline__ void fma2(unsigned long long& d,
                                     unsigned long long a, unsigned long long b) {
    asm("fma.rn.f32x2 %0, %1, %2, %0;" : "+l"(d) : "l"(a), "l"(b));
}
__device__ __forceinline__ float2 unpack2(unsigned long long v) {
    float2 f;
    asm("mov.b64 {%0, %1}, %2;" : "=f"(f.x), "=f"(f.y) : "l"(v));
    return f;
}
__device__ __forceinline__ unsigned f2mono(float f) {
    unsigned u = __float_as_uint(f);
    return (u & 0x80000000u) ? ~u : (u | 0x80000000u);
}

// ---------------- kernel 0: fused QKV projection (proven) ----------------
__global__ void proj_kernel(const float* __restrict__ x,
                            const float* __restrict__ Wq, const float* __restrict__ bq,
                            const float* __restrict__ Wk, const float* __restrict__ bk,
                            const float* __restrict__ Wv, const float* __restrict__ bv)
{
    extern __shared__ float sm[];
    float* xs   = sm;                 // [64][128]
    float* Wall = xs + 64 * 128;      // [128][64]
    float* ball = Wall + 128 * 64;    // [128]

    const int b  = blockIdx.x >> 5;
    const int n0 = (blockIdx.x & 31) * 128;
    const int t  = threadIdx.x;

    for (int i = t; i < 32 * 64; i += 256) Wall[i] = Wq[i];
    for (int i = t; i < 32 * 64; i += 256) Wall[32 * 64 + i] = Wk[i];
    for (int i = t; i < 64 * 64; i += 256) Wall[64 * 64 + i] = Wv[i];
    if (t < 32)        ball[t] = bq[t];
    else if (t < 64)   ball[t] = bk[t - 32];
    else if (t < 128)  ball[t] = bv[t - 64];

    const float* xb = x + (size_t)b * CDIM * NPIX;
    for (int i = t; i < CDIM * 128; i += 256) {
        int c = i >> 7, p = i & 127;
        xs[c * 128 + p] = xb[(size_t)c * NPIX + n0 + p];
    }
    __syncthreads();

    const int p = t & 127;
    const int h = t >> 7;

    if (h == 0) {
        for (int oo = 0; oo < 64; oo++) {
            float acc = ball[oo];
            const float* wr = Wall + oo * 64;
            #pragma unroll 16
            for (int c = 0; c < 64; c++) acc = fmaf(wr[c], xs[c * 128 + p], acc);
            if (oo < 32) g_q[((size_t)b * KD + oo) * NPIX + n0 + p] = acc;
            else         g_k[((size_t)b * KD + (oo - 32)) * NPIX + n0 + p] = acc;
        }
    } else {
        float vacc[64];
        #pragma unroll
        for (int od = 0; od < 64; od++) vacc[od] = ball[64 + od];
        for (int c = 0; c < 64; c++) {
            float xv = xs[c * 128 + p];
            #pragma unroll
            for (int od = 0; od < 64; od++)
                vacc[od] = fmaf(Wall[(64 + od) * 64 + c], xv, vacc[od]);
        }
        float4* vd = (float4*)(g_v + ((size_t)b * NPIX + n0 + p) * OD);
        #pragma unroll
        for (int q4 = 0; q4 < 16; q4++)
            vd[q4] = make_float4(vacc[4 * q4], vacc[4 * q4 + 1], vacc[4 * q4 + 2], vacc[4 * q4 + 3]);
    }
}

// ---------------- kernel 1 ----------------
// grid: BATCH*1024 CTAs, 256 threads, 4 rows/CTA, 2 CTAs/SM.
__global__ void __launch_bounds__(THREADS, 2)
attn_kernel(const float* __restrict__ x, const float* __restrict__ gamma,
            float* __restrict__ out)
{
    extern __shared__ float sm[];
    // byte layout (qs2 first for 8B alignment)
    unsigned long long* qs2  = (unsigned long long*)sm;               // [4][32] u64
    float*          e      = (float*)(qs2 + ROWS * KD);               // [4][4096]
    float*          wl     = e + ROWS * NPIX;                         // [4][LISTCAP]
    int*            il     = (int*)(wl + ROWS * LISTCAP);             // [4][LISTCAP]
    int*            hist   = il + ROWS * LISTCAP;                     // [4][HPAD]
    float*          obuf   = (float*)(hist + ROWS * HPAD);            // [4][2][64]
    float*          wmaxs  = obuf + ROWS * 2 * OD;                    // [8][4]
    float*          rowmax = wmaxs + 8 * ROWS;                        // [4]
    float*          zsum   = rowmax + ROWS;                           // [4]
    unsigned*       b0s    = (unsigned*)(zsum + ROWS);                // [4]
    int*            rem1   = (int*)(b0s + ROWS);                      // [4]
    unsigned*       pfxs   = (unsigned*)(rem1 + ROWS);                // [4]
    int*            rems   = (int*)(pfxs + ROWS);                     // [4]
    int*            cnt    = rems + ROWS;                             // [4]
    int*            ccnt   = cnt + ROWS;                              // [4]
    unsigned short* cdi    = (unsigned short*)(ccnt + ROWS);          // [4][CANDCAP]

    const int b  = blockIdx.x >> 10;
    const int i0 = (blockIdx.x & 1023) * ROWS;
    const int t    = threadIdx.x;
    const int lane = t & 31;
    const int warp = t >> 5;

    if (t < ROWS) { cnt[t] = 0; ccnt[t] = 0; zsum[t] = 0.f; }
    for (int i = t; i < ROWS * HPAD; i += THREADS) hist[i] = 0;
    if (t < ROWS * KD) {
        int kd = t & 31, rr = t >> 5;
        float qv = g_q[((size_t)b * KD + kd) * NPIX + i0 + rr];
        qs2[rr * 32 + kd] = pack2(qv, qv);
    }
    __syncthreads();

    // ===== phase E: energy, 4 rows x 16 cols per thread =====
    {
        const ulonglong2* kq = (const ulonglong2*)(g_k + (size_t)b * KD * NPIX);
        unsigned long long acc[ROWS][8];
        #pragma unroll
        for (int r = 0; r < ROWS; r++)
            #pragma unroll
            for (int c = 0; c < 8; c++) acc[r][c] = 0ull;

        for (int kd = 0; kd < KD; kd++) {          // NO unroll: keep regs minimal
            ulonglong2 k0 = kq[kd * (NPIX / 4) + 4 * t];
            ulonglong2 k1 = kq[kd * (NPIX / 4) + 4 * t + 1];
            ulonglong2 k2 = kq[kd * (NPIX / 4) + 4 * t + 2];
            ulonglong2 k3 = kq[kd * (NPIX / 4) + 4 * t + 3];
            #pragma unroll
            for (int r = 0; r < ROWS; r++) {
                unsigned long long qq = qs2[r * 32 + kd];  // LDS.64 broadcast
                fma2(acc[r][0], k0.x, qq);
                fma2(acc[r][1], k0.y, qq);
                fma2(acc[r][2], k1.x, qq);
                fma2(acc[r][3], k1.y, qq);
                fma2(acc[r][4], k2.x, qq);
                fma2(acc[r][5], k2.y, qq);
                fma2(acc[r][6], k3.x, qq);
                fma2(acc[r][7], k3.y, qq);
            }
        }

        // epilogue: store e, per-row max, 10-bit histogram from registers
        #pragma unroll
        for (int r = 0; r < ROWS; r++) {
            float v[16];
            #pragma unroll
            for (int c = 0; c < 8; c++) {
                float2 p = unpack2(acc[r][c]);
                v[2 * c] = p.x; v[2 * c + 1] = p.y;
            }
            float4* ep = (float4*)(e + r * NPIX + 16 * t);
            ep[0] = make_float4(v[0],  v[1],  v[2],  v[3]);
            ep[1] = make_float4(v[4],  v[5],  v[6],  v[7]);
            ep[2] = make_float4(v[8],  v[9],  v[10], v[11]);
            ep[3] = make_float4(v[12], v[13], v[14], v[15]);
            float m = v[0];
            #pragma unroll
            for (int i = 1; i < 16; i++) m = fmaxf(m, v[i]);
            #pragma unroll
            for (int o = 16; o; o >>= 1) m = fmaxf(m, __shfl_xor_sync(0xffffffffu, m, o));
            if (lane == 0) wmaxs[warp * ROWS + r] = m;

            int* h = hist + r * HPAD;
            #pragma unroll
            for (int i = 0; i < 16; i++) {
                unsigned bx = f2mono(v[i]) >> 22;   // 10-bit bin
                unsigned peers = __match_any_sync(0xffffffffu, bx);
                if (lane == (__ffs(peers) - 1)) atomicAdd(&h[(int)bx], __popc(peers));
            }
        }
    }
    __syncthreads();
    if (t < ROWS) {
        float m = wmaxs[t];
        #pragma unroll
        for (int w = 1; w < 8; w++) m = fmaxf(m, wmaxs[w * ROWS + t]);
        rowmax[t] = m;
    }
    __syncthreads();

    // ===== boundary bin b0 per row (warp w = row w), 1024 bins, 32/lane =====
    if (warp < ROWS) {
        const int rr = warp;
        int* h = hist + rr * HPAD;
        int bb0 = NBIN0 - 1 - 32 * lane;
        int lsum = 0;
        for (int u2 = 0; u2 < 32; u2++) lsum += h[bb0 - u2];
        int incl = lsum;
        #pragma unroll
        for (int o = 1; o < 32; o <<= 1) {
            int vv = __shfl_up_sync(0xffffffffu, incl, o);
            if (lane >= o) incl += vv;
        }
        int above = incl - lsum;
        if (above < KK && KK <= incl) {
            int cum = above, bsel = bb0;
            for (int u2 = 0; u2 < 32; u2++) {
                int c = h[bb0 - u2];
                if (cum + c >= KK) { bsel = bb0 - u2; break; }
                cum += c;
            }
            b0s[rr]  = (unsigned)bsel;
            rem1[rr] = KK - cum;
        }
    }
    __syncthreads();

    // ===== classify scan over e (one pass, uniform trips) =====
    const int rg  = t >> 6;       // 64 threads (2 warps) per row
    const int t64 = t & 63;
    float* erow = e + rg * NPIX;
    const float m = rowmax[rg];
    const unsigned B0 = b0s[rg];
    float zpart = 0.f;
    for (int j = t64; j < NPIX; j += 64) {
        float v = erow[j];
        unsigned u = f2mono(v);
        unsigned byt = u >> 22;
        bool sure = (byt > B0);
        unsigned bs = __ballot_sync(0xffffffffu, sure);
        if (sure) {
            float w = __expf(v - m);
            zpart += w;
            int ldr = __ffs(bs) - 1, base = 0;
            if (lane == ldr) base = atomicAdd(&cnt[rg], __popc(bs));
            base = __shfl_sync(bs, base, ldr);
            int pos = base + __popc(bs & ((1u << lane) - 1u));
            if (pos < LISTCAP) { il[rg * LISTCAP + pos] = j; wl[rg * LISTCAP + pos] = w; }
        }
        bool cand = (byt == B0);
        unsigned bc = __ballot_sync(0xffffffffu, cand);
        if (cand) {
            int ldr = __ffs(bc) - 1, base = 0;
            if (lane == ldr) base = atomicAdd(&ccnt[rg], __popc(bc));
            base = __shfl_sync(bc, base, ldr);
            int pos = base + __popc(bc & ((1u << lane) - 1u));
            if (pos < CANDCAP) cdi[rg * CANDCAP + pos] = (unsigned short)j;
        }
    }
    __syncthreads();

    // ===== radix over candidates: remaining 22 bits in passes {8,8,6} =====
    {
        int C = ccnt[rg]; if (C > CANDCAP) C = CANDCAP;
        const int Cpad = (C + 63) & ~63;
        unsigned pfx = B0;
        int rem = rem1[rg];
        int* h = hist + rg * HPAD;
        const unsigned short* cdr = cdi + rg * CANDCAP;

        #pragma unroll
        for (int pass = 0; pass < 3; pass++) {
            const int nb      = (pass == 2) ? 64 : 256;
            const int shift   = (pass == 0) ? 14 : (pass == 1) ? 6 : 0;
            const int pshift  = (pass == 0) ? 22 : (pass == 1) ? 14 : 6;
            const int nbits   = (pass == 2) ? 6 : 8;
            for (int i = t64; i < nb; i += 64) h[i] = 0;
            __syncthreads();
            for (int i = t64; i < Cpad; i += 64) {
                bool valid = (i < C);
                unsigned u = valid ? f2mono(erow[cdr[i]]) : 0u;
                bool match = valid && ((u >> pshift) == pfx);
                unsigned bin = (u >> shift) & (unsigned)(nb - 1);
                unsigned key = match ? bin : 0xffffffffu;
                unsigned peers = __match_any_sync(0xffffffffu, key);
                if (match && lane == (__ffs(peers) - 1))
                    atomicAdd(&h[bin], __popc(peers));
            }
            __syncthreads();
            if (t64 < 32) {
                const int per = nb / 32;
                int bb0 = nb - 1 - per * lane;
                int lsum = 0;
                for (int u2 = 0; u2 < per; u2++) lsum += h[bb0 - u2];
                int incl = lsum;
                #pragma unroll
                for (int o = 1; o < 32; o <<= 1) {
                    int vv = __shfl_up_sync(0xffffffffu, incl, o);
                    if (lane >= o) incl += vv;
                }
                int above = incl - lsum;
                if (above < rem && rem <= incl) {
                    int cum = above, bsel = bb0;
                    for (int u2 = 0; u2 < per; u2++) {
                        int c = h[bb0 - u2];
                        if (cum + c >= rem) { bsel = bb0 - u2; break; }
                        cum += c;
                    }
                    pfxs[rg] = (pfx << nbits) | (unsigned)bsel;
                    rems[rg] = rem - cum;
                }
            }
            __syncthreads();
            pfx = pfxs[rg];
            rem = rems[rg];
        }

        // ===== final candidate scan: u >= exact 32-bit threshold =====
        const unsigned T = pfx;
        for (int i = t64; i < Cpad; i += 64) {
            bool valid = (i < C);
            int idx = valid ? (int)cdr[i] : 0;
            float v = 0.f;
            unsigned u = 0;
            if (valid) { v = erow[idx]; u = f2mono(v); }
            bool sel = valid && (u >= T);
            unsigned bs = __ballot_sync(0xffffffffu, sel);
            if (sel) {
                float w = __expf(v - m);
                zpart += w;
                int ldr = __ffs(bs) - 1, base = 0;
                if (lane == ldr) base = atomicAdd(&cnt[rg], __popc(bs));
                base = __shfl_sync(bs, base, ldr);
                int pos = base + __popc(bs & ((1u << lane) - 1u));
                if (pos < LISTCAP) { il[rg * LISTCAP + pos] = idx; wl[rg * LISTCAP + pos] = w; }
            }
        }
    }
    #pragma unroll
    for (int o = 16; o; o >>= 1) zpart += __shfl_xor_sync(0xffffffffu, zpart, o);
    if (lane == 0) atomicAdd(&zsum[rg], zpart);
    __syncthreads();

    // ===== phase PV: sparse gather, 2 warps/row, x4 unroll =====
    {
        int n = cnt[rg]; if (n > LISTCAP) n = LISTCAP;
        const int s = t64 >> 5;
        const float* vb = g_v + (size_t)b * NPIX * OD;
        const int*   ilr = il + rg * LISTCAP;
        const float* wlr = wl + rg * LISTCAP;

        int half  = (n + 1) >> 1;
        int start = s * half;
        int end   = start + half; if (end > n) end = n;

        float2 o2 = make_float2(0.f, 0.f);
        int tix = start;
        for (; tix + 4 <= end; tix += 4) {
            int j0 = ilr[tix], j1 = ilr[tix + 1], j2 = ilr[tix + 2], j3 = ilr[tix + 3];
            float w0 = wlr[tix], w1 = wlr[tix + 1], w2 = wlr[tix + 2], w3 = wlr[tix + 3];
            float2 v0 = ((const float2*)(vb + (size_t)j0 * OD))[lane];
            float2 v1 = ((const float2*)(vb + (size_t)j1 * OD))[lane];
            float2 v2 = ((const float2*)(vb + (size_t)j2 * OD))[lane];
            float2 v3 = ((const float2*)(vb + (size_t)j3 * OD))[lane];
            o2.x = fmaf(w0, v0.x, o2.x); o2.y = fmaf(w0, v0.y, o2.y);
            o2.x = fmaf(w1, v1.x, o2.x); o2.y = fmaf(w1, v1.y, o2.y);
            o2.x = fmaf(w2, v2.x, o2.x); o2.y = fmaf(w2, v2.y, o2.y);
            o2.x = fmaf(w3, v3.x, o2.x); o2.y = fmaf(w3, v3.y, o2.y);
        }
        for (; tix < end; tix++) {
            int jj = ilr[tix];
            float w = wlr[tix];
            float2 vv = ((const float2*)(vb + (size_t)jj * OD))[lane];
            o2.x = fmaf(w, vv.x, o2.x); o2.y = fmaf(w, vv.y, o2.y);
        }
        ((float2*)(obuf + (rg * 2 + s) * OD))[lane] = o2;
    }
    __syncthreads();

    // ===== epilogue: 256 threads = 4 rows x 64 channels =====
    {
        const float g = gamma[0];
        const int r2 = t & 3, c = t >> 2;
        float a = obuf[(r2 * 2 + 0) * OD + c] + obuf[(r2 * 2 + 1) * OD + c];
        const float invZ = 1.f / (zsum[r2] + EPSF);
        const size_t oix = ((size_t)b * CDIM + c) * NPIX + i0 + r2;
        out[oix] = g * a * invZ + x[oix];
    }
}

// ---------------- launch ----------------
extern "C" void kernel_launch(void* const* d_in, const int* in_sizes, int n_in,
                              void* d_out, int out_size)
{
    const float* x     = (const float*)d_in[0];
    const float* Wq    = (const float*)d_in[1];
    const float* bq    = (const float*)d_in[2];
    const float* Wk    = (const float*)d_in[3];
    const float* bk    = (const float*)d_in[4];
    const float* Wv    = (const float*)d_in[5];
    const float* bv    = (const float*)d_in[6];
    const float* gamma = (const float*)d_in[7];
    float* out = (float*)d_out;

    (void)in_sizes; (void)n_in; (void)out_size;

    const int SMEM_PROJ = (64 * 128 + 128 * 64 + 128) * 4;
    const int SMEM_ATTN = ROWS * KD * 8                 // qs2 (u64)
                        + (ROWS * NPIX                  // e
                         + ROWS * LISTCAP               // wl
                         + ROWS * LISTCAP               // il
                         + ROWS * HPAD                  // hist
                         + ROWS * 2 * OD                // obuf
                         + 8 * ROWS                     // wmaxs
                         + ROWS * 8) * 4                // rowmax..ccnt
                        + ROWS * CANDCAP * 2;           // cdi (u16)

    cudaFuncSetAttribute(proj_kernel, cudaFuncAttributeMaxDynamicSharedMemorySize, SMEM_PROJ);
    cudaFuncSetAttribute(attn_kernel, cudaFuncAttributeMaxDynamicSharedMemorySize, SMEM_ATTN);

    proj_kernel<<<BATCH * 32, 256, SMEM_PROJ>>>(x, Wq, bq, Wk, bk, Wv, bv);
    attn_kernel<<<BATCH * (NPIX / ROWS), THREADS, SMEM_ATTN>>>(x, gamma, out);
}

// round 8
// speedup vs baseline: 1.4103x; 1.1543x over previous
#include <cuda_runtime.h>
#include <math.h>

#define BATCH 4
#define CDIM  64
#define KD    32
#define OD    64
#define NPIX  4096
#define KK    409
#define EPSF  1e-10f
#define LISTCAP 448
#define CANDCAP 1024
#define NBIN0   1024

// ---------------- scratch ----------------
__device__ __align__(16) float g_q[BATCH * KD * NPIX];        // [b][kd][n]
__device__ __align__(16) float g_k[BATCH * KD * NPIX];        // [b][kd][n]
__device__ __align__(16) float g_v[BATCH * NPIX * OD];        // [b][n][od]
__device__ __align__(16) float g_e[(size_t)BATCH * NPIX * NPIX]; // [b][i][j] 256MB

// ---------------- f32x2 helpers ----------------
__device__ __forceinline__ unsigned long long pack2(float a, float b) {
    unsigned long long r;
    asm("mov.b64 %0, {%1, %2};" : "=l"(r) : "f"(a), "f"(b));
    return r;
}
__device__ __forceinline__ void fma2(unsigned long long& d,
                                     unsigned long long a, unsigned long long b) {
    asm("fma.rn.f32x2 %0, %1, %2, %0;" : "+l"(d) : "l"(a), "l"(b));
}
__device__ __forceinline__ float2 unpack2(unsigned long long v) {
    float2 f;
    asm("mov.b64 {%0, %1}, %2;" : "=f"(f.x), "=f"(f.y) : "l"(v));
    return f;
}
__device__ __forceinline__ unsigned f2mono(float f) {
    unsigned u = __float_as_uint(f);
    return (u & 0x80000000u) ? ~u : (u | 0x80000000u);
}

// ---------------- kernel 0: fused QKV projection (proven) ----------------
__global__ void proj_kernel(const float* __restrict__ x,
                            const float* __restrict__ Wq, const float* __restrict__ bq,
                            const float* __restrict__ Wk, const float* __restrict__ bk,
                            const float* __restrict__ Wv, const float* __restrict__ bv)
{
    extern __shared__ float sm[];
    float* xs   = sm;                 // [64][128]
    float* Wall = xs + 64 * 128;      // [128][64]
    float* ball = Wall + 128 * 64;    // [128]

    const int b  = blockIdx.x >> 5;
    const int n0 = (blockIdx.x & 31) * 128;
    const int t  = threadIdx.x;

    for (int i = t; i < 32 * 64; i += 256) Wall[i] = Wq[i];
    for (int i = t; i < 32 * 64; i += 256) Wall[32 * 64 + i] = Wk[i];
    for (int i = t; i < 64 * 64; i += 256) Wall[64 * 64 + i] = Wv[i];
    if (t < 32)        ball[t] = bq[t];
    else if (t < 64)   ball[t] = bk[t - 32];
    else if (t < 128)  ball[t] = bv[t - 64];

    const float* xb = x + (size_t)b * CDIM * NPIX;
    for (int i = t; i < CDIM * 128; i += 256) {
        int c = i >> 7, p = i & 127;
        xs[c * 128 + p] = xb[(size_t)c * NPIX + n0 + p];
    }
    __syncthreads();

    const int p = t & 127;
    const int h = t >> 7;

    if (h == 0) {
        for (int oo = 0; oo < 64; oo++) {
            float acc = ball[oo];
            const float* wr = Wall + oo * 64;
            #pragma unroll 16
            for (int c = 0; c < 64; c++) acc = fmaf(wr[c], xs[c * 128 + p], acc);
            if (oo < 32) g_q[((size_t)b * KD + oo) * NPIX + n0 + p] = acc;
            else         g_k[((size_t)b * KD + (oo - 32)) * NPIX + n0 + p] = acc;
        }
    } else {
        float vacc[64];
        #pragma unroll
        for (int od = 0; od < 64; od++) vacc[od] = ball[64 + od];
        for (int c = 0; c < 64; c++) {
            float xv = xs[c * 128 + p];
            #pragma unroll
            for (int od = 0; od < 64; od++)
                vacc[od] = fmaf(Wall[(64 + od) * 64 + c], xv, vacc[od]);
        }
        float4* vd = (float4*)(g_v + ((size_t)b * NPIX + n0 + p) * OD);
        #pragma unroll
        for (int q4 = 0; q4 < 16; q4++)
            vd[q4] = make_float4(vacc[4 * q4], vacc[4 * q4 + 1], vacc[4 * q4 + 2], vacc[4 * q4 + 3]);
    }
}

// ---------------- kernel 1: energy GEMM (tiled, e -> gmem) ----------------
// grid (32 jT, 32 iT, 4 b), 256 threads, 2 CTAs/SM. Each thread: 8i x 8j.
__global__ void __launch_bounds__(256, 2)
energy_kernel()
{
    __shared__ float Qs[32 * 128];   // [kd][ii]
    __shared__ float Ks[32 * 128];   // [kd][jj]

    const int b  = blockIdx.z;
    const int iT = blockIdx.y * 128;
    const int jT = blockIdx.x * 128;
    const int t  = threadIdx.x;

    const float4* qg = (const float4*)(g_q + (size_t)b * KD * NPIX);
    const float4* kg = (const float4*)(g_k + (size_t)b * KD * NPIX);
    for (int m = t; m < 1024; m += 256) {
        int kd = m >> 5, f = m & 31;
        ((float4*)Qs)[m] = qg[kd * (NPIX / 4) + (iT >> 2) + f];
        ((float4*)Ks)[m] = kg[kd * (NPIX / 4) + (jT >> 2) + f];
    }
    __syncthreads();

    const int tx = t & 15, ty = t >> 4;

    unsigned long long acc[8][4];
    #pragma unroll
    for (int ri = 0; ri < 8; ri++)
        #pragma unroll
        for (int c = 0; c < 4; c++) acc[ri][c] = 0ull;

    #pragma unroll 1
    for (int kd = 0; kd < KD; kd++) {
        const float4* qa = (const float4*)(Qs + kd * 128 + ty * 8);
        float4 a0 = qa[0], a1 = qa[1];
        const ulonglong2* kb = (const ulonglong2*)(Ks + kd * 128 + tx * 8);
        ulonglong2 b01 = kb[0], b23 = kb[1];
        float av[8] = {a0.x, a0.y, a0.z, a0.w, a1.x, a1.y, a1.z, a1.w};
        #pragma unroll
        for (int ri = 0; ri < 8; ri++) {
            unsigned long long aa = pack2(av[ri], av[ri]);
            fma2(acc[ri][0], b01.x, aa);
            fma2(acc[ri][1], b01.y, aa);
            fma2(acc[ri][2], b23.x, aa);
            fma2(acc[ri][3], b23.y, aa);
        }
    }

    float* eb = g_e + ((size_t)b * NPIX + iT) * NPIX + jT;
    #pragma unroll
    for (int ri = 0; ri < 8; ri++) {
        float2 p0 = unpack2(acc[ri][0]), p1 = unpack2(acc[ri][1]);
        float2 p2 = unpack2(acc[ri][2]), p3 = unpack2(acc[ri][3]);
        float4* dst = (float4*)(eb + (size_t)(ty * 8 + ri) * NPIX + tx * 8);
        dst[0] = make_float4(p0.x, p0.y, p1.x, p1.y);
        dst[1] = make_float4(p2.x, p2.y, p3.x, p3.y);
    }
}

// ---------------- kernel 2: per-row select + softmax + PV ----------------
// grid BATCH*NPIX CTAs (one per query row), 128 threads, ~27KB smem, 6 CTAs/SM.
__global__ void __launch_bounds__(128, 6)
select_pv_kernel(const float* __restrict__ x, const float* __restrict__ gamma,
                 float* __restrict__ out)
{
    __shared__ float          es[NPIX];          // e row, 16KB
    __shared__ int            hist[NBIN0];       // 4KB (reused 256-bin in radix)
    __shared__ float          wl[LISTCAP];
    __shared__ int            il[LISTCAP];
    __shared__ unsigned short cdi[CANDCAP];
    __shared__ float          obuf[4][OD];
    __shared__ float          wred[4];
    __shared__ float          rowmax_s, zsum_s;
    __shared__ int            cnt_s, ccnt_s, rem_s;
    __shared__ unsigned       pfx_s, b0_s;

    const int bi = blockIdx.x;
    const int b  = bi >> 12;
    const int i  = bi & (NPIX - 1);
    const int t    = threadIdx.x;
    const int lane = t & 31;
    const int warp = t >> 5;

    if (t == 0) { cnt_s = 0; ccnt_s = 0; zsum_s = 0.f; }
    for (int m = t; m < NBIN0; m += 128) hist[m] = 0;
    __syncthreads();

    // ---- stream e row in; rowmax + 10-bit histogram from registers ----
    const float4* er = (const float4*)(g_e + ((size_t)b * NPIX + i) * NPIX);
    float mx = -1e30f;
    #pragma unroll
    for (int k = 0; k < 8; k++) {
        int f = t + 128 * k;
        float4 v4 = er[f];
        ((float4*)es)[f] = v4;
        float vv[4] = {v4.x, v4.y, v4.z, v4.w};
        #pragma unroll
        for (int c = 0; c < 4; c++) {
            mx = fmaxf(mx, vv[c]);
            unsigned bx = f2mono(vv[c]) >> 22;
            unsigned peers = __match_any_sync(0xffffffffu, bx);
            if (lane == (__ffs(peers) - 1)) atomicAdd(&hist[(int)bx], __popc(peers));
        }
    }
    #pragma unroll
    for (int o = 16; o; o >>= 1) mx = fmaxf(mx, __shfl_xor_sync(0xffffffffu, mx, o));
    if (lane == 0) wred[warp] = mx;
    __syncthreads();
    if (t == 0)
        rowmax_s = fmaxf(fmaxf(wred[0], wred[1]), fmaxf(wred[2], wred[3]));

    // ---- b0 scan (warp 0, 32 bins per lane, descending) ----
    if (warp == 0) {
        int bb0 = NBIN0 - 1 - 32 * lane;
        int lsum = 0;
        for (int u2 = 0; u2 < 32; u2++) lsum += hist[bb0 - u2];
        int incl = lsum;
        #pragma unroll
        for (int o = 1; o < 32; o <<= 1) {
            int vv = __shfl_up_sync(0xffffffffu, incl, o);
            if (lane >= o) incl += vv;
        }
        int above = incl - lsum;
        if (above < KK && KK <= incl) {
            int cum = above, bsel = bb0;
            for (int u2 = 0; u2 < 32; u2++) {
                int c = hist[bb0 - u2];
                if (cum + c >= KK) { bsel = bb0 - u2; break; }
                cum += c;
            }
            b0_s  = (unsigned)bsel;
            rem_s = KK - cum;
        }
    }
    __syncthreads();

    const float    m  = rowmax_s;
    const unsigned B0 = b0_s;
    float zpart = 0.f;

    // ---- classify (uniform 32 trips) ----
    for (int j = t; j < NPIX; j += 128) {
        float v = es[j];
        unsigned u = f2mono(v);
        unsigned byt = u >> 22;
        bool sure = (byt > B0);
        unsigned bs = __ballot_sync(0xffffffffu, sure);
        if (sure) {
            float w = __expf(v - m);
            zpart += w;
            int ldr = __ffs(bs) - 1, base = 0;
            if (lane == ldr) base = atomicAdd(&cnt_s, __popc(bs));
            base = __shfl_sync(bs, base, ldr);
            int pos = base + __popc(bs & ((1u << lane) - 1u));
            if (pos < LISTCAP) { il[pos] = j; wl[pos] = w; }
        }
        bool cand = (byt == B0);
        unsigned bc = __ballot_sync(0xffffffffu, cand);
        if (cand) {
            int ldr = __ffs(bc) - 1, base = 0;
            if (lane == ldr) base = atomicAdd(&ccnt_s, __popc(bc));
            base = __shfl_sync(bc, base, ldr);
            int pos = base + __popc(bc & ((1u << lane) - 1u));
            if (pos < CANDCAP) cdi[pos] = (unsigned short)j;
        }
    }
    __syncthreads();

    // ---- radix over candidates: remaining 22 bits {8,8,6}, padded loops ----
    {
        int C = ccnt_s; if (C > CANDCAP) C = CANDCAP;
        const int Cpad = (C + 127) & ~127;
        unsigned pfx = B0;
        int rem = rem_s;

        #pragma unroll
        for (int pass = 0; pass < 3; pass++) {
            const int nb     = (pass == 2) ? 64 : 256;
            const int shift  = (pass == 0) ? 14 : (pass == 1) ? 6 : 0;
            const int pshift = (pass == 0) ? 22 : (pass == 1) ? 14 : 6;
            const int nbits  = (pass == 2) ? 6 : 8;
            for (int q = t; q < nb; q += 128) hist[q] = 0;
            __syncthreads();
            for (int q = t; q < Cpad; q += 128) {
                bool valid = (q < C);
                unsigned u = valid ? f2mono(es[cdi[q]]) : 0u;
                bool match = valid && ((u >> pshift) == pfx);
                unsigned bin = (u >> shift) & (unsigned)(nb - 1);
                unsigned key = match ? bin : 0xffffffffu;
                unsigned peers = __match_any_sync(0xffffffffu, key);
                if (match && lane == (__ffs(peers) - 1))
                    atomicAdd(&hist[bin], __popc(peers));
            }
            __syncthreads();
            if (warp == 0) {
                const int per = nb / 32;
                int bb0 = nb - 1 - per * lane;
                int lsum = 0;
                for (int u2 = 0; u2 < per; u2++) lsum += hist[bb0 - u2];
                int incl = lsum;
                #pragma unroll
                for (int o = 1; o < 32; o <<= 1) {
                    int vv = __shfl_up_sync(0xffffffffu, incl, o);
                    if (lane >= o) incl += vv;
                }
                int above = incl - lsum;
                if (above < rem && rem <= incl) {
                    int cum = above, bsel = bb0;
                    for (int u2 = 0; u2 < per; u2++) {
                        int c = hist[bb0 - u2];
                        if (cum + c >= rem) { bsel = bb0 - u2; break; }
                        cum += c;
                    }
                    pfx_s = (pfx << nbits) | (unsigned)bsel;
                    rem_s = rem - cum;
                }
            }
            __syncthreads();
            pfx = pfx_s;
            rem = rem_s;
        }

        // ---- final candidate scan: u >= exact 32-bit threshold ----
        const unsigned T = pfx;
        for (int q = t; q < Cpad; q += 128) {
            bool valid = (q < C);
            int idx = valid ? (int)cdi[q] : 0;
            float v = 0.f;
            unsigned u = 0;
            if (valid) { v = es[idx]; u = f2mono(v); }
            bool sel = valid && (u >= T);
            unsigned bs = __ballot_sync(0xffffffffu, sel);
            if (sel) {
                float w = __expf(v - m);
                zpart += w;
                int ldr = __ffs(bs) - 1, base = 0;
                if (lane == ldr) base = atomicAdd(&cnt_s, __popc(bs));
                base = __shfl_sync(bs, base, ldr);
                int pos = base + __popc(bs & ((1u << lane) - 1u));
                if (pos < LISTCAP) { il[pos] = idx; wl[pos] = w; }
            }
        }
    }
    #pragma unroll
    for (int o = 16; o; o >>= 1) zpart += __shfl_xor_sync(0xffffffffu, zpart, o);
    if (lane == 0) atomicAdd(&zsum_s, zpart);
    __syncthreads();

    // ---- PV: 4 warps split the list; lane covers 2 od; x4 unroll ----
    {
        int n = cnt_s; if (n > LISTCAP) n = LISTCAP;
        const float* vb = g_v + (size_t)b * NPIX * OD;
        int quarter = (n + 3) >> 2;
        int start = warp * quarter;
        int end   = start + quarter; if (end > n) end = n;

        float2 o2 = make_float2(0.f, 0.f);
        int tix = start;
        for (; tix + 4 <= end; tix += 4) {
            int j0 = il[tix], j1 = il[tix + 1], j2 = il[tix + 2], j3 = il[tix + 3];
            float w0 = wl[tix], w1 = wl[tix + 1], w2 = wl[tix + 2], w3 = wl[tix + 3];
            float2 v0 = ((const float2*)(vb + (size_t)j0 * OD))[lane];
            float2 v1 = ((const float2*)(vb + (size_t)j1 * OD))[lane];
            float2 v2 = ((const float2*)(vb + (size_t)j2 * OD))[lane];
            float2 v3 = ((const float2*)(vb + (size_t)j3 * OD))[lane];
            o2.x = fmaf(w0, v0.x, o2.x); o2.y = fmaf(w0, v0.y, o2.y);
            o2.x = fmaf(w1, v1.x, o2.x); o2.y = fmaf(w1, v1.y, o2.y);
            o2.x = fmaf(w2, v2.x, o2.x); o2.y = fmaf(w2, v2.y, o2.y);
            o2.x = fmaf(w3, v3.x, o2.x); o2.y = fmaf(w3, v3.y, o2.y);
        }
        for (; tix < end; tix++) {
            int jj = il[tix];
            float w = wl[tix];
            float2 vv = ((const float2*)(vb + (size_t)jj * OD))[lane];
            o2.x = fmaf(w, vv.x, o2.x); o2.y = fmaf(w, vv.y, o2.y);
        }
        ((float2*)&obuf[warp][0])[lane] = o2;
    }
    __syncthreads();

    // ---- epilogue: 64 threads, one channel each ----
    if (t < CDIM) {
        const float g = gamma[0];
        float a = obuf[0][t] + obuf[1][t] + obuf[2][t] + obuf[3][t];
        const float invZ = 1.f / (zsum_s + EPSF);
        const size_t oix = ((size_t)b * CDIM + t) * NPIX + i;
        out[oix] = g * a * invZ + x[oix];
    }
}

// ---------------- launch ----------------
extern "C" void kernel_launch(void* const* d_in, const int* in_sizes, int n_in,
                              void* d_out, int out_size)
{
    const float* x     = (const float*)d_in[0];
    const float* Wq    = (const float*)d_in[1];
    const float* bq    = (const float*)d_in[2];
    const float* Wk    = (const float*)d_in[3];
    const float* bk    = (const float*)d_in[4];
    const float* Wv    = (const float*)d_in[5];
    const float* bv    = (const float*)d_in[6];
    const float* gamma = (const float*)d_in[7];
    float* out = (float*)d_out;

    (void)in_sizes; (void)n_in; (void)out_size;

    const int SMEM_PROJ = (64 * 128 + 128 * 64 + 128) * 4;
    cudaFuncSetAttribute(proj_kernel, cudaFuncAttributeMaxDynamicSharedMemorySize, SMEM_PROJ);

    proj_kernel<<<BATCH * 32, 256, SMEM_PROJ>>>(x, Wq, bq, Wk, bk, Wv, bv);

    dim3 egrid(NPIX / 128, NPIX / 128, BATCH);
    energy_kernel<<<egrid, 256>>>();

    select_pv_kernel<<<BATCH * NPIX, 128>>>(x, gamma, out);
}

// round 9
// speedup vs baseline: 1.4738x; 1.0450x over previous
#include <cuda_runtime.h>
#include <cuda_fp16.h>
#include <math.h>

#define BATCH 4
#define CDIM  64
#define KD    32
#define OD    64
#define NPIX  4096
#define KK    409
#define EPSF  1e-10f
#define LISTCAP 448
#define CANDCAP 1024
#define NBIN0   1024

// ---------------- scratch ----------------
__device__ __align__(16) float   g_q[BATCH * KD * NPIX];           // [b][kd][n]
__device__ __align__(16) float   g_k[BATCH * KD * NPIX];           // [b][kd][n]
__device__ __align__(16) __half2 g_vh[BATCH * NPIX * OD / 2];      // [b][n][od/2]
__device__ __align__(16) float   g_e[(size_t)BATCH * NPIX * NPIX]; // [b][i][j]

// ---------------- f32x2 helpers ----------------
__device__ __forceinline__ unsigned long long pack2(float a, float b) {
    unsigned long long r;
    asm("mov.b64 %0, {%1, %2};" : "=l"(r) : "f"(a), "f"(b));
    return r;
}
__device__ __forceinline__ void fma2(unsigned long long& d,
                                     unsigned long long a, unsigned long long b) {
    asm("fma.rn.f32x2 %0, %1, %2, %0;" : "+l"(d) : "l"(a), "l"(b));
}
__device__ __forceinline__ float2 unpack2(unsigned long long v) {
    float2 f;
    asm("mov.b64 {%0, %1}, %2;" : "=f"(f.x), "=f"(f.y) : "l"(v));
    return f;
}
__device__ __forceinline__ unsigned f2mono(float f) {
    unsigned u = __float_as_uint(f);
    return (u & 0x80000000u) ? ~u : (u | 0x80000000u);
}

// ---------------- kernel 0: fused QKV projection (retiled: 64 px/CTA) ----------------
// grid: BATCH*64, 256 threads: group 0 -> q, 1 -> k, 2 -> v[0:32], 3 -> v[32:64]
__global__ void __launch_bounds__(256, 4)
proj_kernel(const float* __restrict__ x,
            const float* __restrict__ Wq, const float* __restrict__ bq,
            const float* __restrict__ Wk, const float* __restrict__ bk,
            const float* __restrict__ Wv, const float* __restrict__ bv)
{
    __shared__ float xs[64 * 64];     // [c][p]
    __shared__ float Wall[128 * 64];  // rows 0-31 Wq, 32-63 Wk, 64-127 Wv
    __shared__ float ball[128];

    const int b  = blockIdx.x >> 6;
    const int n0 = (blockIdx.x & 63) * 64;
    const int t  = threadIdx.x;

    for (int i = t; i < 32 * 64; i += 256) Wall[i] = Wq[i];
    for (int i = t; i < 32 * 64; i += 256) Wall[32 * 64 + i] = Wk[i];
    for (int i = t; i < 64 * 64; i += 256) Wall[64 * 64 + i] = Wv[i];
    if (t < 32)        ball[t] = bq[t];
    else if (t < 64)   ball[t] = bk[t - 32];
    else if (t < 128)  ball[t] = bv[t - 64];

    const float* xb = x + (size_t)b * CDIM * NPIX;
    for (int i = t; i < CDIM * 64; i += 256) {
        int c = i >> 6, p = i & 63;
        xs[c * 64 + p] = xb[(size_t)c * NPIX + n0 + p];
    }
    __syncthreads();

    const int p = t & 63;
    const int h = t >> 6;

    if (h < 2) {
        // h==0: q outputs 0..31 ; h==1: k outputs 0..31
        const int ob = h * 32;
        float* dstbase = (h == 0) ? g_q : g_k;
        for (int oo = 0; oo < 32; oo++) {
            float acc = ball[ob + oo];
            const float* wr = Wall + (ob + oo) * 64;
            #pragma unroll 16
            for (int c = 0; c < 64; c++) acc = fmaf(wr[c], xs[c * 64 + p], acc);
            dstbase[((size_t)b * KD + oo) * NPIX + n0 + p] = acc;
        }
    } else {
        // v outputs [h2*32, h2*32+32)
        const int h2 = h - 2;
        float vacc[32];
        #pragma unroll
        for (int od = 0; od < 32; od++) vacc[od] = ball[64 + h2 * 32 + od];
        for (int c = 0; c < 64; c++) {
            float xv = xs[c * 64 + p];
            #pragma unroll
            for (int od = 0; od < 32; od++)
                vacc[od] = fmaf(Wall[(64 + h2 * 32 + od) * 64 + c], xv, vacc[od]);
        }
        __half2* vd = g_vh + ((size_t)b * NPIX + n0 + p) * (OD / 2) + h2 * 16;
        #pragma unroll
        for (int q2 = 0; q2 < 16; q2++)
            vd[q2] = __floats2half2_rn(vacc[2 * q2], vacc[2 * q2 + 1]);
    }
}

// ---------------- kernel 1: energy GEMM (tiled, e -> gmem; R8-proven) ----------------
__global__ void __launch_bounds__(256, 2)
energy_kernel()
{
    __shared__ float Qs[32 * 128];   // [kd][ii]
    __shared__ float Ks[32 * 128];   // [kd][jj]

    const int b  = blockIdx.z;
    const int iT = blockIdx.y * 128;
    const int jT = blockIdx.x * 128;
    const int t  = threadIdx.x;

    const float4* qg = (const float4*)(g_q + (size_t)b * KD * NPIX);
    const float4* kg = (const float4*)(g_k + (size_t)b * KD * NPIX);
    for (int m = t; m < 1024; m += 256) {
        int kd = m >> 5, f = m & 31;
        ((float4*)Qs)[m] = qg[kd * (NPIX / 4) + (iT >> 2) + f];
        ((float4*)Ks)[m] = kg[kd * (NPIX / 4) + (jT >> 2) + f];
    }
    __syncthreads();

    const int tx = t & 15, ty = t >> 4;

    unsigned long long acc[8][4];
    #pragma unroll
    for (int ri = 0; ri < 8; ri++)
        #pragma unroll
        for (int c = 0; c < 4; c++) acc[ri][c] = 0ull;

    #pragma unroll 1
    for (int kd = 0; kd < KD; kd++) {
        const float4* qa = (const float4*)(Qs + kd * 128 + ty * 8);
        float4 a0 = qa[0], a1 = qa[1];
        const ulonglong2* kb = (const ulonglong2*)(Ks + kd * 128 + tx * 8);
        ulonglong2 b01 = kb[0], b23 = kb[1];
        float av[8] = {a0.x, a0.y, a0.z, a0.w, a1.x, a1.y, a1.z, a1.w};
        #pragma unroll
        for (int ri = 0; ri < 8; ri++) {
            unsigned long long aa = pack2(av[ri], av[ri]);
            fma2(acc[ri][0], b01.x, aa);
            fma2(acc[ri][1], b01.y, aa);
            fma2(acc[ri][2], b23.x, aa);
            fma2(acc[ri][3], b23.y, aa);
        }
    }

    float* eb = g_e + ((size_t)b * NPIX + iT) * NPIX + jT;
    #pragma unroll
    for (int ri = 0; ri < 8; ri++) {
        float2 p0 = unpack2(acc[ri][0]), p1 = unpack2(acc[ri][1]);
        float2 p2 = unpack2(acc[ri][2]), p3 = unpack2(acc[ri][3]);
        float4* dst = (float4*)(eb + (size_t)(ty * 8 + ri) * NPIX + tx * 8);
        dst[0] = make_float4(p0.x, p0.y, p1.x, p1.y);
        dst[1] = make_float4(p2.x, p2.y, p3.x, p3.y);
    }
}

// ---------------- kernel 2: per-row select + softmax + PV (fp16 V) ----------------
// grid BATCH*NPIX CTAs (one per query row), 128 threads, ~27KB smem, 8 CTAs/SM.
__global__ void __launch_bounds__(128, 8)
select_pv_kernel(const float* __restrict__ x, const float* __restrict__ gamma,
                 float* __restrict__ out)
{
    __shared__ float          es[NPIX];          // e row, 16KB
    __shared__ int            hist[NBIN0];       // 4KB (reused 256-bin in radix)
    __shared__ float          wl[LISTCAP];
    __shared__ int            il[LISTCAP];
    __shared__ unsigned short cdi[CANDCAP];
    __shared__ float          obuf[4][OD];
    __shared__ float          wred[4];
    __shared__ float          rowmax_s, zsum_s;
    __shared__ int            cnt_s, ccnt_s, rem_s;
    __shared__ unsigned       pfx_s, b0_s;

    const int bi = blockIdx.x;
    const int b  = bi >> 12;
    const int i  = bi & (NPIX - 1);
    const int t    = threadIdx.x;
    const int lane = t & 31;
    const int warp = t >> 5;

    if (t == 0) { cnt_s = 0; ccnt_s = 0; zsum_s = 0.f; }
    for (int m = t; m < NBIN0; m += 128) hist[m] = 0;
    __syncthreads();

    // ---- stream e row in; rowmax + 10-bit histogram from registers ----
    const float4* er = (const float4*)(g_e + ((size_t)b * NPIX + i) * NPIX);
    float mx = -1e30f;
    #pragma unroll
    for (int k = 0; k < 8; k++) {
        int f = t + 128 * k;
        float4 v4 = er[f];
        ((float4*)es)[f] = v4;
        float vv[4] = {v4.x, v4.y, v4.z, v4.w};
        #pragma unroll
        for (int c = 0; c < 4; c++) {
            mx = fmaxf(mx, vv[c]);
            unsigned bx = f2mono(vv[c]) >> 22;
            unsigned peers = __match_any_sync(0xffffffffu, bx);
            if (lane == (__ffs(peers) - 1)) atomicAdd(&hist[(int)bx], __popc(peers));
        }
    }
    #pragma unroll
    for (int o = 16; o; o >>= 1) mx = fmaxf(mx, __shfl_xor_sync(0xffffffffu, mx, o));
    if (lane == 0) wred[warp] = mx;
    __syncthreads();
    if (t == 0)
        rowmax_s = fmaxf(fmaxf(wred[0], wred[1]), fmaxf(wred[2], wred[3]));

    // ---- b0 scan (warp 0, 32 bins per lane, descending) ----
    if (warp == 0) {
        int bb0 = NBIN0 - 1 - 32 * lane;
        int lsum = 0;
        for (int u2 = 0; u2 < 32; u2++) lsum += hist[bb0 - u2];
        int incl = lsum;
        #pragma unroll
        for (int o = 1; o < 32; o <<= 1) {
            int vv = __shfl_up_sync(0xffffffffu, incl, o);
            if (lane >= o) incl += vv;
        }
        int above = incl - lsum;
        if (above < KK && KK <= incl) {
            int cum = above, bsel = bb0;
            for (int u2 = 0; u2 < 32; u2++) {
                int c = hist[bb0 - u2];
                if (cum + c >= KK) { bsel = bb0 - u2; break; }
                cum += c;
            }
            b0_s  = (unsigned)bsel;
            rem_s = KK - cum;
        }
    }
    __syncthreads();

    const float    m  = rowmax_s;
    const unsigned B0 = b0_s;
    float zpart = 0.f;

    // ---- classify (uniform 32 trips) ----
    for (int j = t; j < NPIX; j += 128) {
        float v = es[j];
        unsigned u = f2mono(v);
        unsigned byt = u >> 22;
        bool sure = (byt > B0);
        unsigned bs = __ballot_sync(0xffffffffu, sure);
        if (sure) {
            float w = __expf(v - m);
            zpart += w;
            int ldr = __ffs(bs) - 1, base = 0;
            if (lane == ldr) base = atomicAdd(&cnt_s, __popc(bs));
            base = __shfl_sync(bs, base, ldr);
            int pos = base + __popc(bs & ((1u << lane) - 1u));
            if (pos < LISTCAP) { il[pos] = j; wl[pos] = w; }
        }
        bool cand = (byt == B0);
        unsigned bc = __ballot_sync(0xffffffffu, cand);
        if (cand) {
            int ldr = __ffs(bc) - 1, base = 0;
            if (lane == ldr) base = atomicAdd(&ccnt_s, __popc(bc));
            base = __shfl_sync(bc, base, ldr);
            int pos = base + __popc(bc & ((1u << lane) - 1u));
            if (pos < CANDCAP) cdi[pos] = (unsigned short)j;
        }
    }
    __syncthreads();

    // ---- radix over candidates: remaining 22 bits {8,8,6}, padded loops ----
    {
        int C = ccnt_s; if (C > CANDCAP) C = CANDCAP;
        const int Cpad = (C + 127) & ~127;
        unsigned pfx = B0;
        int rem = rem_s;

        #pragma unroll
        for (int pass = 0; pass < 3; pass++) {
            const int nb     = (pass == 2) ? 64 : 256;
            const int shift  = (pass == 0) ? 14 : (pass == 1) ? 6 : 0;
            const int pshift = (pass == 0) ? 22 : (pass == 1) ? 14 : 6;
            const int nbits  = (pass == 2) ? 6 : 8;
            for (int q = t; q < nb; q += 128) hist[q] = 0;
            __syncthreads();
            for (int q = t; q < Cpad; q += 128) {
                bool valid = (q < C);
                unsigned u = valid ? f2mono(es[cdi[q]]) : 0u;
                bool match = valid && ((u >> pshift) == pfx);
                unsigned bin = (u >> shift) & (unsigned)(nb - 1);
                unsigned key = match ? bin : 0xffffffffu;
                unsigned peers = __match_any_sync(0xffffffffu, key);
                if (match && lane == (__ffs(peers) - 1))
                    atomicAdd(&hist[bin], __popc(peers));
            }
            __syncthreads();
            if (warp == 0) {
                const int per = nb / 32;
                int bb0 = nb - 1 - per * lane;
                int lsum = 0;
                for (int u2 = 0; u2 < per; u2++) lsum += hist[bb0 - u2];
                int incl = lsum;
                #pragma unroll
                for (int o = 1; o < 32; o <<= 1) {
                    int vv = __shfl_up_sync(0xffffffffu, incl, o);
                    if (lane >= o) incl += vv;
                }
                int above = incl - lsum;
                if (above < rem && rem <= incl) {
                    int cum = above, bsel = bb0;
                    for (int u2 = 0; u2 < per; u2++) {
                        int c = hist[bb0 - u2];
                        if (cum + c >= rem) { bsel = bb0 - u2; break; }
                        cum += c;
                    }
                    pfx_s = (pfx << nbits) | (unsigned)bsel;
                    rem_s = rem - cum;
                }
            }
            __syncthreads();
            pfx = pfx_s;
            rem = rem_s;
        }

        // ---- final candidate scan: u >= exact 32-bit threshold ----
        const unsigned T = pfx;
        for (int q = t; q < Cpad; q += 128) {
            bool valid = (q < C);
            int idx = valid ? (int)cdi[q] : 0;
            float v = 0.f;
            unsigned u = 0;
            if (valid) { v = es[idx]; u = f2mono(v); }
            bool sel = valid && (u >= T);
            unsigned bs = __ballot_sync(0xffffffffu, sel);
            if (sel) {
                float w = __expf(v - m);
                zpart += w;
                int ldr = __ffs(bs) - 1, base = 0;
                if (lane == ldr) base = atomicAdd(&cnt_s, __popc(bs));
                base = __shfl_sync(bs, base, ldr);
                int pos = base + __popc(bs & ((1u << lane) - 1u));
                if (pos < LISTCAP) { il[pos] = idx; wl[pos] = w; }
            }
        }
    }
    #pragma unroll
    for (int o = 16; o; o >>= 1) zpart += __shfl_xor_sync(0xffffffffu, zpart, o);
    if (lane == 0) atomicAdd(&zsum_s, zpart);
    __syncthreads();

    // ---- PV: 4 warps split the list; fp16 V, lane covers 2 od; x4 unroll ----
    {
        int n = cnt_s; if (n > LISTCAP) n = LISTCAP;
        const __half2* vb = g_vh + (size_t)b * NPIX * (OD / 2);
        int quarter = (n + 3) >> 2;
        int start = warp * quarter;
        int end   = start + quarter; if (end > n) end = n;

        float2 o2 = make_float2(0.f, 0.f);
        int tix = start;
        for (; tix + 4 <= end; tix += 4) {
            int j0 = il[tix], j1 = il[tix + 1], j2 = il[tix + 2], j3 = il[tix + 3];
            float w0 = wl[tix], w1 = wl[tix + 1], w2 = wl[tix + 2], w3 = wl[tix + 3];
            float2 v0 = __half22float2(vb[(size_t)j0 * (OD / 2) + lane]);
            float2 v1 = __half22float2(vb[(size_t)j1 * (OD / 2) + lane]);
            float2 v2 = __half22float2(vb[(size_t)j2 * (OD / 2) + lane]);
            float2 v3 = __half22float2(vb[(size_t)j3 * (OD / 2) + lane]);
            o2.x = fmaf(w0, v0.x, o2.x); o2.y = fmaf(w0, v0.y, o2.y);
            o2.x = fmaf(w1, v1.x, o2.x); o2.y = fmaf(w1, v1.y, o2.y);
            o2.x = fmaf(w2, v2.x, o2.x); o2.y = fmaf(w2, v2.y, o2.y);
            o2.x = fmaf(w3, v3.x, o2.x); o2.y = fmaf(w3, v3.y, o2.y);
        }
        for (; tix < end; tix++) {
            int jj = il[tix];
            float w = wl[tix];
            float2 vv = __half22float2(vb[(size_t)jj * (OD / 2) + lane]);
            o2.x = fmaf(w, vv.x, o2.x); o2.y = fmaf(w, vv.y, o2.y);
        }
        ((float2*)&obuf[warp][0])[lane] = o2;
    }
    __syncthreads();

    // ---- epilogue: 64 threads, one channel each ----
    if (t < CDIM) {
        const float g = gamma[0];
        float a = obuf[0][t] + obuf[1][t] + obuf[2][t] + obuf[3][t];
        const float invZ = 1.f / (zsum_s + EPSF);
        const size_t oix = ((size_t)b * CDIM + t) * NPIX + i;
        out[oix] = g * a * invZ + x[oix];
    }
}

// ---------------- launch ----------------
extern "C" void kernel_launch(void* const* d_in, const int* in_sizes, int n_in,
                              void* d_out, int out_size)
{
    const float* x     = (const float*)d_in[0];
    const float* Wq    = (const float*)d_in[1];
    const float* bq    = (const float*)d_in[2];
    const float* Wk    = (const float*)d_in[3];
    const float* bk    = (const float*)d_in[4];
    const float* Wv    = (const float*)d_in[5];
    const float* bv    = (const float*)d_in[6];
    const float* gamma = (const float*)d_in[7];
    float* out = (float*)d_out;

    (void)in_sizes; (void)n_in; (void)out_size;

    proj_kernel<<<BATCH * 64, 256>>>(x, Wq, bq, Wk, bk, Wv, bv);

    dim3 egrid(NPIX / 128, NPIX / 128, BATCH);
    energy_kernel<<<egrid, 256>>>();

    select_pv_kernel<<<BATCH * NPIX, 128>>>(x, gamma, out);
}